// round 1
// baseline (speedup 1.0000x reference)
#include <cuda_runtime.h>
#include <cuda_bf16.h>
#include <math.h>

// ---------------------------------------------------------------------------
// Problem constants
// ---------------------------------------------------------------------------
#define BATCH   2
#define SEQ     2048
#define DMODEL  1024
#define DINNER  2048
#define DSTATE  16
#define DTRANK  64
#define KCONV   4
#define DFF     4096
#define TOK     (BATCH*SEQ)          // 4096 tokens
#define NCH     16                   // scan chunks
#define CHL     128                  // chunk length (NCH*CHL == SEQ)
#define CHANNELS (BATCH*DINNER)      // 4096 scan channels

// ---------------------------------------------------------------------------
// Device scratch (static allocation; harness forbids cudaMalloc)
// ---------------------------------------------------------------------------
__device__ float g_hnorm [TOK*DMODEL];
__device__ float g_xz    [TOK*2*DINNER];
__device__ float g_xconv [TOK*DINNER];
__device__ float g_proj  [TOK*96];
__device__ float g_dtn   [TOK*DTRANK];
__device__ float g_Bm    [TOK*DSTATE];
__device__ float g_Cm    [TOK*DSTATE];
__device__ float g_dt    [TOK*DINNER];
__device__ float g_yg    [TOK*DINNER];
__device__ float g_hidden[TOK*DMODEL];
__device__ float g_hn    [TOK*DMODEL];
__device__ float g_gate  [TOK*DFF];
__device__ float g_up    [TOK*DFF];
__device__ float g_Aneg  [DINNER*DSTATE];
__device__ int   g_afast [DINNER];
__device__ float g_Aprod [NCH*CHANNELS*DSTATE];
__device__ float g_h0    [NCH*CHANNELS*DSTATE];
__device__ float g_hin   [NCH*CHANNELS*DSTATE];

// ---------------------------------------------------------------------------
// Small helpers
// ---------------------------------------------------------------------------
__device__ __forceinline__ unsigned long long pk2(float lo, float hi) {
    union { float2 f; unsigned long long u; } c;
    c.f.x = lo; c.f.y = hi; return c.u;
}
__device__ __forceinline__ float2 unpk2(unsigned long long v) {
    union { float2 f; unsigned long long u; } c;
    c.u = v; return c.f;
}
// Packed dual-FMA (Blackwell f32x2 pipe) — only reachable via PTX.
__device__ __forceinline__ void ffma2(unsigned long long &d,
                                      unsigned long long a,
                                      unsigned long long b) {
    asm("fma.rn.f32x2 %0, %1, %2, %0;" : "+l"(d) : "l"(a), "l"(b));
}
__device__ __forceinline__ float sigmoidf_(float x) { return 1.f / (1.f + __expf(-x)); }
__device__ __forceinline__ float siluf_(float x)    { return x * sigmoidf_(x); }
__device__ __forceinline__ float softplusf_(float x){ return x > 20.f ? x : log1pf(__expf(x)); }

// ---------------------------------------------------------------------------
// RMSNorm over last dim == 1024 (one block per token, 256 threads, float4)
// ---------------------------------------------------------------------------
__global__ void rmsnorm_k(const float* __restrict__ x, const float* __restrict__ w,
                          float* __restrict__ o) {
    int row = blockIdx.x, tid = threadIdx.x;
    const float4* xr = reinterpret_cast<const float4*>(x + (size_t)row * DMODEL);
    float4 v = xr[tid];
    float ss = v.x*v.x + v.y*v.y + v.z*v.z + v.w*v.w;
#pragma unroll
    for (int off = 16; off > 0; off >>= 1) ss += __shfl_xor_sync(0xffffffffu, ss, off);
    __shared__ float sred[8];
    __shared__ float sinv;
    int lane = tid & 31, wid = tid >> 5;
    if (lane == 0) sred[wid] = ss;
    __syncthreads();
    if (tid == 0) {
        float t = 0.f;
#pragma unroll
        for (int i = 0; i < 8; i++) t += sred[i];
        sinv = rsqrtf(t / (float)DMODEL + 1e-6f);
    }
    __syncthreads();
    float inv = sinv;
    float4 wv = reinterpret_cast<const float4*>(w)[tid];
    float4 r;
    r.x = v.x*inv*wv.x; r.y = v.y*inv*wv.y; r.z = v.z*inv*wv.z; r.w = v.w*inv*wv.w;
    reinterpret_cast<float4*>(o + (size_t)row * DMODEL)[tid] = r;
}

// ---------------------------------------------------------------------------
// Main tiled GEMM: C[MxN] = A[MxK]*B[KxN], 128x128 tile, BK=16, 256 threads,
// 8x8 micro-tile per thread via packed f32x2 FMAs.
// EPI: 0 none, 1 bias+softplus, 2 add residual.
// Requires M%128==0, N%128==0, K%16==0 (true for all call sites).
// ---------------------------------------------------------------------------
template<int EPI>
__global__ __launch_bounds__(256) void gemm128_k(
    const float* __restrict__ A, const float* __restrict__ B, float* __restrict__ C,
    int M, int N, int K, const float* __restrict__ bias, const float* __restrict__ res)
{
    __shared__ float As[16][132];   // transposed A tile, padded (conflict-free)
    __shared__ float Bs[16][128];
    int tid = threadIdx.x;
    int tx = tid & 15, ty = tid >> 4;
    int m0 = blockIdx.y * 128, n0 = blockIdx.x * 128;

    unsigned long long acc[8][4];
#pragma unroll
    for (int i = 0; i < 8; i++)
#pragma unroll
        for (int j = 0; j < 4; j++) acc[i][j] = 0ull;

    for (int k0 = 0; k0 < K; k0 += 16) {
#pragma unroll
        for (int i = 0; i < 2; i++) {             // A tile: 128x16
            int v = tid + i * 256;
            int r = v >> 2, cv = v & 3;
            float4 t4 = *reinterpret_cast<const float4*>(
                A + (size_t)(m0 + r) * K + k0 + cv * 4);
            As[cv*4+0][r] = t4.x; As[cv*4+1][r] = t4.y;
            As[cv*4+2][r] = t4.z; As[cv*4+3][r] = t4.w;
        }
#pragma unroll
        for (int i = 0; i < 2; i++) {             // B tile: 16x128
            int v = tid + i * 256;
            int r = v >> 5, cv = v & 31;
            *reinterpret_cast<float4*>(&Bs[r][cv*4]) =
                *reinterpret_cast<const float4*>(B + (size_t)(k0 + r) * N + n0 + cv * 4);
        }
        __syncthreads();
#pragma unroll
        for (int kk = 0; kk < 16; kk++) {
            float4 a0 = *reinterpret_cast<const float4*>(&As[kk][ty*8]);
            float4 a1 = *reinterpret_cast<const float4*>(&As[kk][ty*8+4]);
            float4 b0 = *reinterpret_cast<const float4*>(&Bs[kk][tx*8]);
            float4 b1 = *reinterpret_cast<const float4*>(&Bs[kk][tx*8+4]);
            unsigned long long bp[4] = { pk2(b0.x,b0.y), pk2(b0.z,b0.w),
                                         pk2(b1.x,b1.y), pk2(b1.z,b1.w) };
            float av[8] = { a0.x,a0.y,a0.z,a0.w, a1.x,a1.y,a1.z,a1.w };
#pragma unroll
            for (int i = 0; i < 8; i++) {
                unsigned long long a2 = pk2(av[i], av[i]);
#pragma unroll
                for (int j = 0; j < 4; j++) ffma2(acc[i][j], a2, bp[j]);
            }
        }
        __syncthreads();
    }
#pragma unroll
    for (int i = 0; i < 8; i++) {
        int row = m0 + ty * 8 + i;
#pragma unroll
        for (int j = 0; j < 4; j++) {
            int col = n0 + tx * 8 + j * 2;
            float2 v = unpk2(acc[i][j]);
            if (EPI == 1) {
                v.x = softplusf_(v.x + bias[col]);
                v.y = softplusf_(v.y + bias[col + 1]);
            } else if (EPI == 2) {
                float2 r2 = *reinterpret_cast<const float2*>(res + (size_t)row * N + col);
                v.x += r2.x; v.y += r2.y;
            }
            *reinterpret_cast<float2*>(C + (size_t)row * N + col) = v;
        }
    }
}

// ---------------------------------------------------------------------------
// Thin-N GEMM for x_proj (N = 96). Block: 32 rows x 96 cols, BK=64.
// ---------------------------------------------------------------------------
__global__ __launch_bounds__(256) void gemm_thin96_k(
    const float* __restrict__ A, const float* __restrict__ B,
    float* __restrict__ C, int K)
{
    __shared__ float As[32][65];
    __shared__ float Bs[64][96];
    int tid = threadIdx.x;
    int m0 = blockIdx.x * 32;
    int ty = tid >> 5, tx = tid & 31;     // rows ty*4.., cols tx*3..
    float acc[4][3];
#pragma unroll
    for (int i = 0; i < 4; i++)
#pragma unroll
        for (int j = 0; j < 3; j++) acc[i][j] = 0.f;

    for (int k0 = 0; k0 < K; k0 += 64) {
        for (int idx = tid; idx < 32 * 64; idx += 256) {
            int r = idx >> 6, c = idx & 63;
            As[r][c] = A[(size_t)(m0 + r) * K + k0 + c];
        }
        for (int idx = tid; idx < 64 * 96; idx += 256) {
            int r = idx / 96, c = idx - r * 96;
            Bs[r][c] = B[(size_t)(k0 + r) * 96 + c];
        }
        __syncthreads();
#pragma unroll 8
        for (int kk = 0; kk < 64; kk++) {
            float b0 = Bs[kk][tx*3+0], b1 = Bs[kk][tx*3+1], b2 = Bs[kk][tx*3+2];
#pragma unroll
            for (int i = 0; i < 4; i++) {
                float a = As[ty*4+i][kk];
                acc[i][0] = fmaf(a, b0, acc[i][0]);
                acc[i][1] = fmaf(a, b1, acc[i][1]);
                acc[i][2] = fmaf(a, b2, acc[i][2]);
            }
        }
        __syncthreads();
    }
#pragma unroll
    for (int i = 0; i < 4; i++)
#pragma unroll
        for (int j = 0; j < 3; j++)
            C[(size_t)(m0 + ty*4 + i) * 96 + tx*3 + j] = acc[i][j];
}

// ---------------------------------------------------------------------------
// Depthwise causal conv (K=4) + bias + SiLU.  x = xz[..., :DINNER]
// ---------------------------------------------------------------------------
__global__ void conv_silu_k(const float* __restrict__ xz, const float* __restrict__ cw,
                            const float* __restrict__ cb, float* __restrict__ out) {
    int d = blockIdx.x * 256 + threadIdx.x;
    int t = blockIdx.y, b = blockIdx.z;
    const float* xp = xz + ((size_t)(b * SEQ + t)) * (2 * DINNER) + d;
    float w0 = cw[d*4+0], w1 = cw[d*4+1], w2 = cw[d*4+2], w3 = cw[d*4+3];
    float acc = cb[d];
    if (t >= 3) acc = fmaf(xp[-3 * 2 * DINNER], w0, acc);
    if (t >= 2) acc = fmaf(xp[-2 * 2 * DINNER], w1, acc);
    if (t >= 1) acc = fmaf(xp[-1 * 2 * DINNER], w2, acc);
    acc = fmaf(xp[0], w3, acc);
    out[((size_t)(b * SEQ + t)) * DINNER + d] = siluf_(acc);
}

// conv_state[b,d,k] = x[b, SEQ-4+k, d]   (pre-conv x)
__global__ void conv_state_k(const float* __restrict__ xz, float* __restrict__ oc) {
    int i = blockIdx.x * 256 + threadIdx.x;
    if (i >= BATCH * DINNER * KCONV) return;
    int k = i & 3;
    int d = (i >> 2) % DINNER;
    int b = i / (DINNER * KCONV);
    oc[i] = xz[((size_t)(b * SEQ + SEQ - KCONV + k)) * (2 * DINNER) + d];
}

// ---------------------------------------------------------------------------
// Per-token small RMSNorms: dt (64), B (16), C (16).  One warp per token.
// ---------------------------------------------------------------------------
__global__ void norms_small_k(const float* __restrict__ proj,
                              const float* __restrict__ wdt,
                              const float* __restrict__ wb,
                              const float* __restrict__ wc,
                              float* __restrict__ dtn,
                              float* __restrict__ Bm,
                              float* __restrict__ Cm) {
    int t = (blockIdx.x * blockDim.x + threadIdx.x) >> 5;
    int lane = threadIdx.x & 31;
    if (t >= TOK) return;
    const float* p = proj + (size_t)t * 96;
    float a = p[lane], b = p[lane + 32];
    float ss = a*a + b*b;
#pragma unroll
    for (int off = 16; off > 0; off >>= 1) ss += __shfl_xor_sync(0xffffffffu, ss, off);
    float bv = lane < 16 ? p[64 + lane] : 0.f;
    float ssb = bv * bv;
#pragma unroll
    for (int off = 16; off > 0; off >>= 1) ssb += __shfl_xor_sync(0xffffffffu, ssb, off);
    float cv = lane < 16 ? p[80 + lane] : 0.f;
    float ssc = cv * cv;
#pragma unroll
    for (int off = 16; off > 0; off >>= 1) ssc += __shfl_xor_sync(0xffffffffu, ssc, off);

    float invd = rsqrtf(ss / 64.f + 1e-6f);
    dtn[(size_t)t*64 + lane]      = a * invd * wdt[lane];
    dtn[(size_t)t*64 + lane + 32] = b * invd * wdt[lane + 32];
    if (lane < 16) {
        Bm[(size_t)t*16 + lane] = bv * rsqrtf(ssb / 16.f + 1e-6f) * wb[lane];
        Cm[(size_t)t*16 + lane] = cv * rsqrtf(ssc / 16.f + 1e-6f) * wc[lane];
    }
}

// ---------------------------------------------------------------------------
// A preprocessing: A = -exp(A_log); detect A_n == (n+1)*A_0 structure so the
// scan can use one exp + 15 muls per step instead of 16 exps.
// ---------------------------------------------------------------------------
__global__ void aprep_k(const float* __restrict__ A_log) {
    int d = blockIdx.x * 256 + threadIdx.x;
    if (d >= DINNER) return;
    float a[16];
#pragma unroll
    for (int n = 0; n < 16; n++) {
        a[n] = -expf(A_log[d * 16 + n]);
        g_Aneg[d * 16 + n] = a[n];
    }
    int ok = a[0] < 0.f;
#pragma unroll
    for (int n = 1; n < 16; n++) {
        float r = a[n] / a[0];
        ok = ok && (fabsf(r - (float)(n + 1)) <= 1e-4f * (float)(n + 1));
    }
    g_afast[d] = ok;
}

// ---------------------------------------------------------------------------
// Selective-scan phase 1: per (channel, chunk) compute cumulative dA product
// and chunk output state assuming zero input state.
// ---------------------------------------------------------------------------
__global__ __launch_bounds__(256) void scan1_k() {
    __shared__ float sB[CHL * 16];
    int d = blockIdx.x * 256 + threadIdx.x;
    int c = blockIdx.y, b = blockIdx.z;
    size_t tok0 = (size_t)b * SEQ + (size_t)c * CHL;
    for (int idx = threadIdx.x; idx < CHL * 16; idx += 256)
        sB[idx] = g_Bm[tok0 * 16 + idx];
    __syncthreads();

    float h[16], Ap[16];
#pragma unroll
    for (int n = 0; n < 16; n++) { h[n] = 0.f; Ap[n] = 1.f; }
    int fast = g_afast[d];
    float A0 = g_Aneg[d * 16];

    if (fast) {
        for (int t = 0; t < CHL; t++) {
            size_t ix = (tok0 + t) * DINNER + d;
            float dtv = g_dt[ix], xv = g_xconv[ix];
            float u = dtv * xv;
            float e = __expf(dtv * A0);
            const float* Bt = &sB[t * 16];
            float p = e;
#pragma unroll
            for (int n = 0; n < 16; n++) {
                h[n] = fmaf(h[n], p, u * Bt[n]);
                Ap[n] *= p;
                p *= e;
            }
        }
    } else {
        float Ar[16];
#pragma unroll
        for (int n = 0; n < 16; n++) Ar[n] = g_Aneg[d * 16 + n];
        for (int t = 0; t < CHL; t++) {
            size_t ix = (tok0 + t) * DINNER + d;
            float dtv = g_dt[ix], xv = g_xconv[ix];
            float u = dtv * xv;
            const float* Bt = &sB[t * 16];
#pragma unroll
            for (int n = 0; n < 16; n++) {
                float da = __expf(dtv * Ar[n]);
                h[n] = fmaf(h[n], da, u * Bt[n]);
                Ap[n] *= da;
            }
        }
    }
    int ch = b * DINNER + d;
    size_t o = ((size_t)c * CHANNELS + ch) * 16;
#pragma unroll
    for (int n = 0; n < 16; n++) { g_Aprod[o + n] = Ap[n]; g_h0[o + n] = h[n]; }
}

// Phase 2: sequential combine across 16 chunks per channel; emits per-chunk
// input states and the final ssm_state.
__global__ void scan2_k(float* __restrict__ ssm_out) {
    int ch = blockIdx.x * 256 + threadIdx.x;
    if (ch >= CHANNELS) return;
    float carry[16];
#pragma unroll
    for (int n = 0; n < 16; n++) carry[n] = 0.f;
    for (int c = 0; c < NCH; c++) {
        size_t o = ((size_t)c * CHANNELS + ch) * 16;
#pragma unroll
        for (int n = 0; n < 16; n++) {
            g_hin[o + n] = carry[n];
            carry[n] = fmaf(g_Aprod[o + n], carry[n], g_h0[o + n]);
        }
    }
#pragma unroll
    for (int n = 0; n < 16; n++) ssm_out[(size_t)ch * 16 + n] = carry[n];
}

// Phase 3: replay with correct initial state, emit gated output
// yg = (sum_n h_n*C_n + x*D_skip) * silu(z)
__global__ __launch_bounds__(256) void scan3_k(const float* __restrict__ Dskip) {
    __shared__ float sB[CHL * 16];
    __shared__ float sC[CHL * 16];
    int d = blockIdx.x * 256 + threadIdx.x;
    int c = blockIdx.y, b = blockIdx.z;
    size_t tok0 = (size_t)b * SEQ + (size_t)c * CHL;
    for (int idx = threadIdx.x; idx < CHL * 16; idx += 256) {
        sB[idx] = g_Bm[tok0 * 16 + idx];
        sC[idx] = g_Cm[tok0 * 16 + idx];
    }
    __syncthreads();

    int ch = b * DINNER + d;
    size_t ho = ((size_t)c * CHANNELS + ch) * 16;
    float h[16];
#pragma unroll
    for (int n = 0; n < 16; n++) h[n] = g_hin[ho + n];
    int fast = g_afast[d];
    float A0 = g_Aneg[d * 16];
    float Dk = Dskip[d];

    if (fast) {
        for (int t = 0; t < CHL; t++) {
            size_t ix = (tok0 + t) * DINNER + d;
            float dtv = g_dt[ix], xv = g_xconv[ix];
            float u = dtv * xv;
            float zv = g_xz[(tok0 + t) * (2 * DINNER) + DINNER + d];
            float e = __expf(dtv * A0);
            const float* Bt = &sB[t * 16];
            const float* Ct = &sC[t * 16];
            float p = e, y = 0.f;
#pragma unroll
            for (int n = 0; n < 16; n++) {
                h[n] = fmaf(h[n], p, u * Bt[n]);
                y = fmaf(h[n], Ct[n], y);
                p *= e;
            }
            float yv = fmaf(xv, Dk, y);
            g_yg[ix] = yv * siluf_(zv);
        }
    } else {
        float Ar[16];
#pragma unroll
        for (int n = 0; n < 16; n++) Ar[n] = g_Aneg[d * 16 + n];
        for (int t = 0; t < CHL; t++) {
            size_t ix = (tok0 + t) * DINNER + d;
            float dtv = g_dt[ix], xv = g_xconv[ix];
            float u = dtv * xv;
            float zv = g_xz[(tok0 + t) * (2 * DINNER) + DINNER + d];
            const float* Bt = &sB[t * 16];
            const float* Ct = &sC[t * 16];
            float y = 0.f;
#pragma unroll
            for (int n = 0; n < 16; n++) {
                float da = __expf(dtv * Ar[n]);
                h[n] = fmaf(h[n], da, u * Bt[n]);
                y = fmaf(h[n], Ct[n], y);
            }
            float yv = fmaf(xv, Dk, y);
            g_yg[ix] = yv * siluf_(zv);
        }
    }
}

// SwiGLU elementwise: g = silu(g) * u
__global__ void swiglu_k(float* __restrict__ g, const float* __restrict__ u, int n) {
    int i = blockIdx.x * 256 + threadIdx.x;
    if (i < n) g[i] = siluf_(g[i]) * u[i];
}

// ---------------------------------------------------------------------------
// Launch
// ---------------------------------------------------------------------------
extern "C" void kernel_launch(void* const* d_in, const int* in_sizes, int n_in,
                              void* d_out, int out_size) {
    (void)in_sizes; (void)n_in; (void)out_size;
    const float* hidden_states = (const float*)d_in[0];
    const float* in_proj_w     = (const float*)d_in[1];
    const float* conv_w        = (const float*)d_in[2];
    const float* conv_b        = (const float*)d_in[3];
    const float* x_proj_w      = (const float*)d_in[4];
    const float* dt_proj_w     = (const float*)d_in[5];
    const float* dt_proj_b     = (const float*)d_in[6];
    const float* dt_ln_w       = (const float*)d_in[7];
    const float* b_ln_w        = (const float*)d_in[8];
    const float* c_ln_w        = (const float*)d_in[9];
    const float* A_log         = (const float*)d_in[10];
    const float* D_skip        = (const float*)d_in[11];
    const float* out_proj_w    = (const float*)d_in[12];
    const float* input_ln_w    = (const float*)d_in[13];
    const float* pre_moe_ln_w  = (const float*)d_in[14];
    const float* gate_w        = (const float*)d_in[15];
    const float* up_w          = (const float*)d_in[16];
    const float* down_w        = (const float*)d_in[17];

    float* out      = (float*)d_out;                         // (B,S,DMODEL)
    float* out_conv = out + (size_t)TOK * DMODEL;            // (B,DINNER,KCONV)
    float* out_ssm  = out_conv + BATCH * DINNER * KCONV;     // (B,DINNER,DSTATE)

    float *hnorm, *xz, *xconv, *proj, *dtn, *Bm, *Cm, *dt, *yg, *hid, *hn, *gate, *up;
    cudaGetSymbolAddress((void**)&hnorm, g_hnorm);
    cudaGetSymbolAddress((void**)&xz,    g_xz);
    cudaGetSymbolAddress((void**)&xconv, g_xconv);
    cudaGetSymbolAddress((void**)&proj,  g_proj);
    cudaGetSymbolAddress((void**)&dtn,   g_dtn);
    cudaGetSymbolAddress((void**)&Bm,    g_Bm);
    cudaGetSymbolAddress((void**)&Cm,    g_Cm);
    cudaGetSymbolAddress((void**)&dt,    g_dt);
    cudaGetSymbolAddress((void**)&yg,    g_yg);
    cudaGetSymbolAddress((void**)&hid,   g_hidden);
    cudaGetSymbolAddress((void**)&hn,    g_hn);
    cudaGetSymbolAddress((void**)&gate,  g_gate);
    cudaGetSymbolAddress((void**)&up,    g_up);

    // 1. input RMSNorm
    rmsnorm_k<<<TOK, 256>>>(hidden_states, input_ln_w, hnorm);
    // 2. in_proj: (4096x1024) @ (1024x4096)
    gemm128_k<0><<<dim3((2*DINNER)/128, TOK/128), 256>>>(
        hnorm, in_proj_w, xz, TOK, 2*DINNER, DMODEL, nullptr, nullptr);
    // 3. causal depthwise conv + SiLU; conv_state extraction
    conv_silu_k<<<dim3(DINNER/256, SEQ, BATCH), 256>>>(xz, conv_w, conv_b, xconv);
    conv_state_k<<<(BATCH*DINNER*KCONV + 255)/256, 256>>>(xz, out_conv);
    // 4. x_proj (thin N=96)
    gemm_thin96_k<<<TOK/32, 256>>>(xconv, x_proj_w, proj, DINNER);
    // 5. dt/B/C RMSNorms
    norms_small_k<<<TOK/8, 256>>>(proj, dt_ln_w, b_ln_w, c_ln_w, dtn, Bm, Cm);
    // 6. dt_proj + bias + softplus
    gemm128_k<1><<<dim3(DINNER/128, TOK/128), 256>>>(
        dtn, dt_proj_w, dt, TOK, DINNER, DTRANK, dt_proj_b, nullptr);
    // 7. selective scan (chunked 3-phase)
    aprep_k<<<DINNER/256, 256>>>(A_log);
    scan1_k<<<dim3(DINNER/256, NCH, BATCH), 256>>>();
    scan2_k<<<CHANNELS/256, 256>>>(out_ssm);
    scan3_k<<<dim3(DINNER/256, NCH, BATCH), 256>>>(D_skip);
    // 8. out_proj + residual
    gemm128_k<2><<<dim3(DMODEL/128, TOK/128), 256>>>(
        yg, out_proj_w, hid, TOK, DMODEL, DINNER, nullptr, hidden_states);
    // 9. MoE MLP block
    rmsnorm_k<<<TOK, 256>>>(hid, pre_moe_ln_w, hn);
    gemm128_k<0><<<dim3(DFF/128, TOK/128), 256>>>(
        hn, gate_w, gate, TOK, DFF, DMODEL, nullptr, nullptr);
    gemm128_k<0><<<dim3(DFF/128, TOK/128), 256>>>(
        hn, up_w, up, TOK, DFF, DMODEL, nullptr, nullptr);
    swiglu_k<<<(TOK*DFF)/256, 256>>>(gate, up, TOK*DFF);
    gemm128_k<2><<<dim3(DMODEL/128, TOK/128), 256>>>(
        gate, down_w, out, TOK, DMODEL, DFF, nullptr, hid);
}

// round 3
// speedup vs baseline: 2.0014x; 2.0014x over previous
#include <cuda_runtime.h>
#include <cuda_bf16.h>
#include <cstdint>
#include <math.h>

// ---------------------------------------------------------------------------
// Problem constants
// ---------------------------------------------------------------------------
#define BATCH   2
#define SEQ     2048
#define DMODEL  1024
#define DINNER  2048
#define DSTATE  16
#define DTRANK  64
#define KCONV   4
#define DFF     4096
#define TOK     (BATCH*SEQ)          // 4096 tokens
#define NCH     16                   // scan chunks
#define CHL     128                  // chunk length
#define CHANNELS (BATCH*DINNER)      // 4096 scan channels

typedef __nv_bfloat16 bf16;

// ---------------------------------------------------------------------------
// Device scratch (static; harness forbids cudaMalloc)
// ---------------------------------------------------------------------------
__device__ float g_xz    [TOK*2*DINNER];
__device__ float g_xconv [TOK*DINNER];
__device__ float g_proj  [TOK*128];
__device__ float g_Bm    [TOK*DSTATE];
__device__ float g_Cm    [TOK*DSTATE];
__device__ float g_dt    [TOK*DINNER];
__device__ float g_hidden[TOK*DMODEL];
__device__ float g_gate  [TOK*DFF];
__device__ float g_up    [TOK*DFF];
__device__ float g_Aneg  [DINNER*DSTATE];
__device__ int   g_afast [DINNER];
__device__ float g_Aprod [NCH*CHANNELS*DSTATE];
__device__ float g_h0    [NCH*CHANNELS*DSTATE];
__device__ float g_hin   [NCH*CHANNELS*DSTATE];

// bf16 split weights (transposed to [N,K])
__device__ bf16 wt_in_h[2*DINNER*DMODEL],  wt_in_l[2*DINNER*DMODEL];
__device__ bf16 wt_x_h [128*DINNER],       wt_x_l [128*DINNER];
__device__ bf16 wt_dt_h[DINNER*DTRANK],    wt_dt_l[DINNER*DTRANK];
__device__ bf16 wt_o_h [DMODEL*DINNER],    wt_o_l [DMODEL*DINNER];
__device__ bf16 wt_g_h [DFF*DMODEL],       wt_g_l [DFF*DMODEL];
__device__ bf16 wt_u_h [DFF*DMODEL],       wt_u_l [DFF*DMODEL];
__device__ bf16 wt_d_h [DMODEL*DFF],       wt_d_l [DMODEL*DFF];

// bf16 split activations
__device__ bf16 a_ln_h [TOK*DMODEL],  a_ln_l [TOK*DMODEL];
__device__ bf16 a_xc_h [TOK*DINNER],  a_xc_l [TOK*DINNER];
__device__ bf16 a_dtn_h[TOK*DTRANK],  a_dtn_l[TOK*DTRANK];
__device__ bf16 a_yg_h [TOK*DINNER],  a_yg_l [TOK*DINNER];
__device__ bf16 a_gu_h [TOK*DFF],     a_gu_l [TOK*DFF];

// ---------------------------------------------------------------------------
// Helpers
// ---------------------------------------------------------------------------
__device__ __forceinline__ float sigmoidf_(float x) { return 1.f / (1.f + __expf(-x)); }
__device__ __forceinline__ float siluf_(float x)    { return x * sigmoidf_(x); }
__device__ __forceinline__ float softplusf_(float x){ return x > 20.f ? x : log1pf(__expf(x)); }

__device__ __forceinline__ void split_bf16(float v, bf16& h, bf16& l) {
    h = __float2bfloat16(v);
    l = __float2bfloat16(v - __bfloat162float(h));
}

__device__ __forceinline__ uint32_t smem_u32(const void* p) {
    uint32_t a;
    asm("{ .reg .u64 t; cvta.to.shared.u64 t, %1; cvt.u32.u64 %0, t; }" : "=r"(a) : "l"(p));
    return a;
}

#define CP16(s, g) \
    asm volatile("cp.async.cg.shared.global [%0], [%1], 16;" :: "r"(s), "l"(g))
#define CP_COMMIT() asm volatile("cp.async.commit_group;" ::: "memory")
#define CP_WAIT1()  asm volatile("cp.async.wait_group 1;"  ::: "memory")

#define LDMX4(r, a)                                                              \
    asm volatile("ldmatrix.sync.aligned.m8n8.x4.shared.b16 {%0,%1,%2,%3}, [%4];" \
        : "=r"((r)[0]), "=r"((r)[1]), "=r"((r)[2]), "=r"((r)[3]) : "r"(a))

__device__ __forceinline__ void mma16816(float* c, const uint32_t* a,
                                         uint32_t b0, uint32_t b1) {
    asm volatile("mma.sync.aligned.m16n8k16.row.col.f32.bf16.bf16.f32 "
        "{%0,%1,%2,%3}, {%4,%5,%6,%7}, {%8,%9}, {%0,%1,%2,%3};"
        : "+f"(c[0]), "+f"(c[1]), "+f"(c[2]), "+f"(c[3])
        : "r"(a[0]), "r"(a[1]), "r"(a[2]), "r"(a[3]), "r"(b0), "r"(b1));
}

// Swizzled byte offset inside a 128-row x 64-byte tile (conflict-free ldmatrix)
__device__ __forceinline__ int tswz(int r, int c16) {
    return r * 64 + ((c16 ^ ((r >> 1) & 3)) << 4);
}

// ---------------------------------------------------------------------------
// bf16 x3-split GEMM on mma.sync: C[M,N] = (Ah+Al)@(Bh+Bl)^T
// A: [M,K] bf16 hi/lo row-major. B: [N,K] bf16 hi/lo row-major.
// Block 128x128, BK=32, 256 threads (8 warps, 4x2), 3-stage cp.async pipeline.
// EPI: 0 none, 1 bias+softplus, 2 +residual.
// ---------------------------------------------------------------------------
#define GSTAGES 3
#define TILEB   8192              // 128 x 32 bf16
#define STAGEB  (4*TILEB)         // Ah, Al, Bh, Bl

template<int EPI>
__global__ __launch_bounds__(256, 1) void gemm_mma(
    const bf16* __restrict__ Ah, const bf16* __restrict__ Al,
    const bf16* __restrict__ Bh, const bf16* __restrict__ Bl,
    float* __restrict__ C, int M, int N, int K,
    const float* __restrict__ bias, const float* __restrict__ res)
{
    extern __shared__ char smem[];
    const int tid  = threadIdx.x;
    const int lane = tid & 31, wid = tid >> 5;
    const int wm = wid & 3, wn = wid >> 2;        // warp grid 4(m) x 2(n)
    const int m0 = blockIdx.y * 128, n0 = blockIdx.x * 128;
    const uint32_t sb = smem_u32(smem);

    // this thread's two 16B chunks per tile
    const int id0 = tid * 2;
    const int r0c = id0 >> 2,      c0c = id0 & 3;
    const int r1c = (id0 + 1) >> 2, c1c = (id0 + 1) & 3;

    float acc[2][8][4];
#pragma unroll
    for (int i = 0; i < 2; i++)
#pragma unroll
        for (int j = 0; j < 8; j++)
#pragma unroll
            for (int q = 0; q < 4; q++) acc[i][j][q] = 0.f;

    const int nIters = K >> 5;

    auto issue = [&](int it, int s) {
        const int kof = it << 5;
        uint32_t d = sb + s * STAGEB;
        const size_t ga0 = (size_t)(m0 + r0c) * K + kof + c0c * 8;
        const size_t ga1 = (size_t)(m0 + r1c) * K + kof + c1c * 8;
        const size_t gb0 = (size_t)(n0 + r0c) * K + kof + c0c * 8;
        const size_t gb1 = (size_t)(n0 + r1c) * K + kof + c1c * 8;
        const int s0 = tswz(r0c, c0c), s1 = tswz(r1c, c1c);
        CP16(d + s0,             Ah + ga0);  CP16(d + s1,             Ah + ga1);
        CP16(d + TILEB + s0,     Al + ga0);  CP16(d + TILEB + s1,     Al + ga1);
        CP16(d + 2*TILEB + s0,   Bh + gb0);  CP16(d + 2*TILEB + s1,   Bh + gb1);
        CP16(d + 3*TILEB + s0,   Bl + gb0);  CP16(d + 3*TILEB + s1,   Bl + gb1);
    };

    issue(0, 0); CP_COMMIT();
    issue(1, 1); CP_COMMIT();

    // ldmatrix address components (row part fixed per lane)
    const int a_r  = wm * 32 + (lane & 15);            // + mt*16
    const int a_cs = lane >> 4;                        // chunk select 0/1
    const int b_r  = wn * 64 + ((lane >> 3) & 2) * 4 + (lane & 7);  // + p*16
    const int b_cs = (lane >> 3) & 1;

    for (int it = 0; it < nIters; ++it) {
        CP_WAIT1();
        __syncthreads();
        const uint32_t base = sb + (it % GSTAGES) * STAGEB;

#pragma unroll
        for (int ks = 0; ks < 2; ks++) {
            uint32_t ah[2][4], al[2][4], bh[4][4], bl[4][4];
#pragma unroll
            for (int mt = 0; mt < 2; mt++) {
                int off = tswz(a_r + mt * 16, ks * 2 + a_cs);
                LDMX4(ah[mt], base + off);
                LDMX4(al[mt], base + TILEB + off);
            }
#pragma unroll
            for (int p = 0; p < 4; p++) {
                int off = tswz(b_r + p * 16, ks * 2 + b_cs);
                LDMX4(bh[p], base + 2*TILEB + off);
                LDMX4(bl[p], base + 3*TILEB + off);
            }
#pragma unroll
            for (int mt = 0; mt < 2; mt++)
#pragma unroll
                for (int p = 0; p < 4; p++) {
                    mma16816(acc[mt][2*p],   ah[mt], bh[p][0], bh[p][1]);
                    mma16816(acc[mt][2*p+1], ah[mt], bh[p][2], bh[p][3]);
                    mma16816(acc[mt][2*p],   al[mt], bh[p][0], bh[p][1]);
                    mma16816(acc[mt][2*p+1], al[mt], bh[p][2], bh[p][3]);
                    mma16816(acc[mt][2*p],   ah[mt], bl[p][0], bl[p][1]);
                    mma16816(acc[mt][2*p+1], ah[mt], bl[p][2], bl[p][3]);
                }
        }
        if (it + 2 < nIters) issue(it + 2, (it + 2) % GSTAGES);
        CP_COMMIT();
    }

    // Epilogue: direct register -> gmem (float2 per fragment half)
#pragma unroll
    for (int mt = 0; mt < 2; mt++) {
        int row0 = m0 + wm * 32 + mt * 16 + (lane >> 2);
#pragma unroll
        for (int nt = 0; nt < 8; nt++) {
            int col = n0 + wn * 64 + nt * 8 + (lane & 3) * 2;
            float2 v0 = { acc[mt][nt][0], acc[mt][nt][1] };
            float2 v1 = { acc[mt][nt][2], acc[mt][nt][3] };
            if (EPI == 1) {
                float b0 = bias[col], b1 = bias[col + 1];
                v0.x = softplusf_(v0.x + b0); v0.y = softplusf_(v0.y + b1);
                v1.x = softplusf_(v1.x + b0); v1.y = softplusf_(v1.y + b1);
            } else if (EPI == 2) {
                float2 r2;
                r2 = *reinterpret_cast<const float2*>(res + (size_t)row0 * N + col);
                v0.x += r2.x; v0.y += r2.y;
                r2 = *reinterpret_cast<const float2*>(res + (size_t)(row0 + 8) * N + col);
                v1.x += r2.x; v1.y += r2.y;
            }
            *reinterpret_cast<float2*>(C + (size_t)row0 * N + col) = v0;
            *reinterpret_cast<float2*>(C + (size_t)(row0 + 8) * N + col) = v1;
        }
    }
}

// ---------------------------------------------------------------------------
// Weight transpose + bf16 split: W[K,Nsrc] fp32 -> T[N,K] bf16 hi/lo (pad 0)
// ---------------------------------------------------------------------------
__global__ void transpose_split_k(const float* __restrict__ W,
                                  bf16* __restrict__ Th, bf16* __restrict__ Tl,
                                  int K, int Nsrc) {
    __shared__ float tile[32][33];
    int n0 = blockIdx.x * 32, k0 = blockIdx.y * 32;
    int tx = threadIdx.x, ty = threadIdx.y;
#pragma unroll
    for (int j = 0; j < 32; j += 8) {
        int n = n0 + tx, k = k0 + ty + j;
        tile[ty + j][tx] = (n < Nsrc) ? W[(size_t)k * Nsrc + n] : 0.f;
    }
    __syncthreads();
#pragma unroll
    for (int j = 0; j < 32; j += 8) {
        int n = n0 + ty + j, k = k0 + tx;
        float v = tile[tx][ty + j];
        bf16 h, lo; split_bf16(v, h, lo);
        Th[(size_t)n * K + k] = h;
        Tl[(size_t)n * K + k] = lo;
    }
}

// ---------------------------------------------------------------------------
// RMSNorm (1024) -> bf16 split
// ---------------------------------------------------------------------------
__global__ void rmsnorm_split_k(const float* __restrict__ x, const float* __restrict__ w,
                                bf16* __restrict__ oh, bf16* __restrict__ ol) {
    int row = blockIdx.x, tid = threadIdx.x;
    float4 v = reinterpret_cast<const float4*>(x + (size_t)row * DMODEL)[tid];
    float ss = v.x*v.x + v.y*v.y + v.z*v.z + v.w*v.w;
#pragma unroll
    for (int off = 16; off > 0; off >>= 1) ss += __shfl_xor_sync(0xffffffffu, ss, off);
    __shared__ float sred[8];
    __shared__ float sinv;
    int lane = tid & 31, wd = tid >> 5;
    if (lane == 0) sred[wd] = ss;
    __syncthreads();
    if (tid == 0) {
        float t = 0.f;
#pragma unroll
        for (int i = 0; i < 8; i++) t += sred[i];
        sinv = rsqrtf(t / (float)DMODEL + 1e-6f);
    }
    __syncthreads();
    float inv = sinv;
    float4 wv = reinterpret_cast<const float4*>(w)[tid];
    float r[4] = { v.x*inv*wv.x, v.y*inv*wv.y, v.z*inv*wv.z, v.w*inv*wv.w };
    size_t base = (size_t)row * DMODEL + tid * 4;
#pragma unroll
    for (int j = 0; j < 4; j++) {
        bf16 h, lo; split_bf16(r[j], h, lo);
        oh[base + j] = h; ol[base + j] = lo;
    }
}

// ---------------------------------------------------------------------------
// Depthwise causal conv (K=4) + bias + SiLU -> fp32 + bf16 split
// ---------------------------------------------------------------------------
__global__ void conv_silu_k(const float* __restrict__ xz, const float* __restrict__ cw,
                            const float* __restrict__ cb, float* __restrict__ out,
                            bf16* __restrict__ oh, bf16* __restrict__ ol) {
    int d = blockIdx.x * 256 + threadIdx.x;
    int t = blockIdx.y, b = blockIdx.z;
    const float* xp = xz + ((size_t)(b * SEQ + t)) * (2 * DINNER) + d;
    float w0 = cw[d*4+0], w1 = cw[d*4+1], w2 = cw[d*4+2], w3 = cw[d*4+3];
    float acc = cb[d];
    if (t >= 3) acc = fmaf(xp[-3 * 2 * DINNER], w0, acc);
    if (t >= 2) acc = fmaf(xp[-2 * 2 * DINNER], w1, acc);
    if (t >= 1) acc = fmaf(xp[-1 * 2 * DINNER], w2, acc);
    acc = fmaf(xp[0], w3, acc);
    float v = siluf_(acc);
    size_t ix = ((size_t)(b * SEQ + t)) * DINNER + d;
    out[ix] = v;
    bf16 h, lo; split_bf16(v, h, lo);
    oh[ix] = h; ol[ix] = lo;
}

__global__ void conv_state_k(const float* __restrict__ xz, float* __restrict__ oc) {
    int i = blockIdx.x * 256 + threadIdx.x;
    if (i >= BATCH * DINNER * KCONV) return;
    int k = i & 3;
    int d = (i >> 2) % DINNER;
    int b = i / (DINNER * KCONV);
    oc[i] = xz[((size_t)(b * SEQ + SEQ - KCONV + k)) * (2 * DINNER) + d];
}

// ---------------------------------------------------------------------------
// Small RMSNorms (proj stride 128): dt(64)->bf16 split, B/C(16)->fp32
// ---------------------------------------------------------------------------
__global__ void norms_small_k(const float* __restrict__ proj,
                              const float* __restrict__ wdt,
                              const float* __restrict__ wb,
                              const float* __restrict__ wc,
                              bf16* __restrict__ dth, bf16* __restrict__ dtl,
                              float* __restrict__ Bm, float* __restrict__ Cm) {
    int t = (blockIdx.x * blockDim.x + threadIdx.x) >> 5;
    int lane = threadIdx.x & 31;
    if (t >= TOK) return;
    const float* p = proj + (size_t)t * 128;
    float a = p[lane], b = p[lane + 32];
    float ss = a*a + b*b;
#pragma unroll
    for (int off = 16; off > 0; off >>= 1) ss += __shfl_xor_sync(0xffffffffu, ss, off);
    float bv = lane < 16 ? p[64 + lane] : 0.f;
    float ssb = bv * bv;
#pragma unroll
    for (int off = 16; off > 0; off >>= 1) ssb += __shfl_xor_sync(0xffffffffu, ssb, off);
    float cv = lane < 16 ? p[80 + lane] : 0.f;
    float ssc = cv * cv;
#pragma unroll
    for (int off = 16; off > 0; off >>= 1) ssc += __shfl_xor_sync(0xffffffffu, ssc, off);

    float invd = rsqrtf(ss / 64.f + 1e-6f);
    float d0 = a * invd * wdt[lane];
    float d1 = b * invd * wdt[lane + 32];
    bf16 h, lo;
    split_bf16(d0, h, lo); dth[(size_t)t*64 + lane] = h;      dtl[(size_t)t*64 + lane] = lo;
    split_bf16(d1, h, lo); dth[(size_t)t*64 + lane + 32] = h; dtl[(size_t)t*64 + lane + 32] = lo;
    if (lane < 16) {
        Bm[(size_t)t*16 + lane] = bv * rsqrtf(ssb / 16.f + 1e-6f) * wb[lane];
        Cm[(size_t)t*16 + lane] = cv * rsqrtf(ssc / 16.f + 1e-6f) * wc[lane];
    }
}

// ---------------------------------------------------------------------------
// A preprocessing + fast-path detection
// ---------------------------------------------------------------------------
__global__ void aprep_k(const float* __restrict__ A_log) {
    int d = blockIdx.x * 256 + threadIdx.x;
    if (d >= DINNER) return;
    float a[16];
#pragma unroll
    for (int n = 0; n < 16; n++) {
        a[n] = -expf(A_log[d * 16 + n]);
        g_Aneg[d * 16 + n] = a[n];
    }
    int ok = a[0] < 0.f;
#pragma unroll
    for (int n = 1; n < 16; n++) {
        float r = a[n] / a[0];
        ok = ok && (fabsf(r - (float)(n + 1)) <= 1e-4f * (float)(n + 1));
    }
    g_afast[d] = ok;
}

// ---------------------------------------------------------------------------
// Selective scan (3-phase chunked)
// ---------------------------------------------------------------------------
__global__ __launch_bounds__(256) void scan1_k() {
    __shared__ float sB[CHL * 16];
    int d = blockIdx.x * 256 + threadIdx.x;
    int c = blockIdx.y, b = blockIdx.z;
    size_t tok0 = (size_t)b * SEQ + (size_t)c * CHL;
    for (int idx = threadIdx.x; idx < CHL * 16; idx += 256)
        sB[idx] = g_Bm[tok0 * 16 + idx];
    __syncthreads();

    float h[16], Ap[16];
#pragma unroll
    for (int n = 0; n < 16; n++) { h[n] = 0.f; Ap[n] = 1.f; }
    int fast = g_afast[d];
    float A0 = g_Aneg[d * 16];

    if (fast) {
        for (int t = 0; t < CHL; t++) {
            size_t ix = (tok0 + t) * DINNER + d;
            float dtv = g_dt[ix], xv = g_xconv[ix];
            float u = dtv * xv;
            float e = __expf(dtv * A0);
            const float* Bt = &sB[t * 16];
            float p = e;
#pragma unroll
            for (int n = 0; n < 16; n++) {
                h[n] = fmaf(h[n], p, u * Bt[n]);
                Ap[n] *= p;
                p *= e;
            }
        }
    } else {
        float Ar[16];
#pragma unroll
        for (int n = 0; n < 16; n++) Ar[n] = g_Aneg[d * 16 + n];
        for (int t = 0; t < CHL; t++) {
            size_t ix = (tok0 + t) * DINNER + d;
            float dtv = g_dt[ix], xv = g_xconv[ix];
            float u = dtv * xv;
            const float* Bt = &sB[t * 16];
#pragma unroll
            for (int n = 0; n < 16; n++) {
                float da = __expf(dtv * Ar[n]);
                h[n] = fmaf(h[n], da, u * Bt[n]);
                Ap[n] *= da;
            }
        }
    }
    int ch = b * DINNER + d;
    size_t o = ((size_t)c * CHANNELS + ch) * 16;
#pragma unroll
    for (int n = 0; n < 16; n++) { g_Aprod[o + n] = Ap[n]; g_h0[o + n] = h[n]; }
}

__global__ void scan2_k(float* __restrict__ ssm_out) {
    int ch = blockIdx.x * 256 + threadIdx.x;
    if (ch >= CHANNELS) return;
    float carry[16];
#pragma unroll
    for (int n = 0; n < 16; n++) carry[n] = 0.f;
    for (int c = 0; c < NCH; c++) {
        size_t o = ((size_t)c * CHANNELS + ch) * 16;
#pragma unroll
        for (int n = 0; n < 16; n++) {
            g_hin[o + n] = carry[n];
            carry[n] = fmaf(g_Aprod[o + n], carry[n], g_h0[o + n]);
        }
    }
#pragma unroll
    for (int n = 0; n < 16; n++) ssm_out[(size_t)ch * 16 + n] = carry[n];
}

__global__ __launch_bounds__(256) void scan3_k(const float* __restrict__ Dskip) {
    __shared__ float sB[CHL * 16];
    __shared__ float sC[CHL * 16];
    int d = blockIdx.x * 256 + threadIdx.x;
    int c = blockIdx.y, b = blockIdx.z;
    size_t tok0 = (size_t)b * SEQ + (size_t)c * CHL;
    for (int idx = threadIdx.x; idx < CHL * 16; idx += 256) {
        sB[idx] = g_Bm[tok0 * 16 + idx];
        sC[idx] = g_Cm[tok0 * 16 + idx];
    }
    __syncthreads();

    int ch = b * DINNER + d;
    size_t ho = ((size_t)c * CHANNELS + ch) * 16;
    float h[16];
#pragma unroll
    for (int n = 0; n < 16; n++) h[n] = g_hin[ho + n];
    int fast = g_afast[d];
    float A0 = g_Aneg[d * 16];
    float Dk = Dskip[d];

    if (fast) {
        for (int t = 0; t < CHL; t++) {
            size_t ix = (tok0 + t) * DINNER + d;
            float dtv = g_dt[ix], xv = g_xconv[ix];
            float u = dtv * xv;
            float zv = g_xz[(tok0 + t) * (2 * DINNER) + DINNER + d];
            float e = __expf(dtv * A0);
            const float* Bt = &sB[t * 16];
            const float* Ct = &sC[t * 16];
            float p = e, y = 0.f;
#pragma unroll
            for (int n = 0; n < 16; n++) {
                h[n] = fmaf(h[n], p, u * Bt[n]);
                y = fmaf(h[n], Ct[n], y);
                p *= e;
            }
            float yv = fmaf(xv, Dk, y) * siluf_(zv);
            bf16 hh, ll; split_bf16(yv, hh, ll);
            a_yg_h[ix] = hh; a_yg_l[ix] = ll;
        }
    } else {
        float Ar[16];
#pragma unroll
        for (int n = 0; n < 16; n++) Ar[n] = g_Aneg[d * 16 + n];
        for (int t = 0; t < CHL; t++) {
            size_t ix = (tok0 + t) * DINNER + d;
            float dtv = g_dt[ix], xv = g_xconv[ix];
            float u = dtv * xv;
            float zv = g_xz[(tok0 + t) * (2 * DINNER) + DINNER + d];
            const float* Bt = &sB[t * 16];
            const float* Ct = &sC[t * 16];
            float y = 0.f;
#pragma unroll
            for (int n = 0; n < 16; n++) {
                float da = __expf(dtv * Ar[n]);
                h[n] = fmaf(h[n], da, u * Bt[n]);
                y = fmaf(h[n], Ct[n], y);
            }
            float yv = fmaf(xv, Dk, y) * siluf_(zv);
            bf16 hh, ll; split_bf16(yv, hh, ll);
            a_yg_h[ix] = hh; a_yg_l[ix] = ll;
        }
    }
}

// SwiGLU -> bf16 split
__global__ void swiglu_split_k(const float* __restrict__ g, const float* __restrict__ u,
                               bf16* __restrict__ oh, bf16* __restrict__ ol, int n) {
    int i = blockIdx.x * 256 + threadIdx.x;
    if (i < n) {
        float v = siluf_(g[i]) * u[i];
        bf16 h, lo; split_bf16(v, h, lo);
        oh[i] = h; ol[i] = lo;
    }
}

// ---------------------------------------------------------------------------
// Launch
// ---------------------------------------------------------------------------
extern "C" void kernel_launch(void* const* d_in, const int* in_sizes, int n_in,
                              void* d_out, int out_size) {
    (void)in_sizes; (void)n_in; (void)out_size;
    const float* hidden_states = (const float*)d_in[0];
    const float* in_proj_w     = (const float*)d_in[1];
    const float* conv_w        = (const float*)d_in[2];
    const float* conv_b        = (const float*)d_in[3];
    const float* x_proj_w      = (const float*)d_in[4];
    const float* dt_proj_w     = (const float*)d_in[5];
    const float* dt_proj_b     = (const float*)d_in[6];
    const float* dt_ln_w       = (const float*)d_in[7];
    const float* b_ln_w        = (const float*)d_in[8];
    const float* c_ln_w        = (const float*)d_in[9];
    const float* A_log         = (const float*)d_in[10];
    const float* D_skip        = (const float*)d_in[11];
    const float* out_proj_w    = (const float*)d_in[12];
    const float* input_ln_w    = (const float*)d_in[13];
    const float* pre_moe_ln_w  = (const float*)d_in[14];
    const float* gate_w        = (const float*)d_in[15];
    const float* up_w          = (const float*)d_in[16];
    const float* down_w        = (const float*)d_in[17];

    float* out      = (float*)d_out;
    float* out_conv = out + (size_t)TOK * DMODEL;
    float* out_ssm  = out_conv + BATCH * DINNER * KCONV;

    float *xz, *xconv, *proj, *Bm, *Cm, *dt, *hid, *gate, *up;
    cudaGetSymbolAddress((void**)&xz,    g_xz);
    cudaGetSymbolAddress((void**)&xconv, g_xconv);
    cudaGetSymbolAddress((void**)&proj,  g_proj);
    cudaGetSymbolAddress((void**)&Bm,    g_Bm);
    cudaGetSymbolAddress((void**)&Cm,    g_Cm);
    cudaGetSymbolAddress((void**)&dt,    g_dt);
    cudaGetSymbolAddress((void**)&hid,   g_hidden);
    cudaGetSymbolAddress((void**)&gate,  g_gate);
    cudaGetSymbolAddress((void**)&up,    g_up);
    bf16 *w_in_h,*w_in_l,*w_x_h,*w_x_l,*w_dt_h,*w_dt_l,*w_o_h,*w_o_l,
         *w_g_h,*w_g_l,*w_u_h,*w_u_l,*w_d_h,*w_d_l;
    cudaGetSymbolAddress((void**)&w_in_h, wt_in_h); cudaGetSymbolAddress((void**)&w_in_l, wt_in_l);
    cudaGetSymbolAddress((void**)&w_x_h,  wt_x_h ); cudaGetSymbolAddress((void**)&w_x_l,  wt_x_l );
    cudaGetSymbolAddress((void**)&w_dt_h, wt_dt_h); cudaGetSymbolAddress((void**)&w_dt_l, wt_dt_l);
    cudaGetSymbolAddress((void**)&w_o_h,  wt_o_h ); cudaGetSymbolAddress((void**)&w_o_l,  wt_o_l );
    cudaGetSymbolAddress((void**)&w_g_h,  wt_g_h ); cudaGetSymbolAddress((void**)&w_g_l,  wt_g_l );
    cudaGetSymbolAddress((void**)&w_u_h,  wt_u_h ); cudaGetSymbolAddress((void**)&w_u_l,  wt_u_l );
    cudaGetSymbolAddress((void**)&w_d_h,  wt_d_h ); cudaGetSymbolAddress((void**)&w_d_l,  wt_d_l );
    bf16 *ln_h,*ln_l,*xc_h,*xc_l,*dtn_h,*dtn_l,*yg_h,*yg_l,*gu_h,*gu_l;
    cudaGetSymbolAddress((void**)&ln_h,  a_ln_h ); cudaGetSymbolAddress((void**)&ln_l,  a_ln_l );
    cudaGetSymbolAddress((void**)&xc_h,  a_xc_h ); cudaGetSymbolAddress((void**)&xc_l,  a_xc_l );
    cudaGetSymbolAddress((void**)&dtn_h, a_dtn_h); cudaGetSymbolAddress((void**)&dtn_l, a_dtn_l);
    cudaGetSymbolAddress((void**)&yg_h,  a_yg_h ); cudaGetSymbolAddress((void**)&yg_l,  a_yg_l );
    cudaGetSymbolAddress((void**)&gu_h,  a_gu_h ); cudaGetSymbolAddress((void**)&gu_l,  a_gu_l );

    constexpr size_t GSM = GSTAGES * STAGEB;   // 98304 bytes
    cudaFuncSetAttribute(gemm_mma<0>, cudaFuncAttributeMaxDynamicSharedMemorySize, GSM);
    cudaFuncSetAttribute(gemm_mma<1>, cudaFuncAttributeMaxDynamicSharedMemorySize, GSM);
    cudaFuncSetAttribute(gemm_mma<2>, cudaFuncAttributeMaxDynamicSharedMemorySize, GSM);

    // Weight transposes + splits
    dim3 tb(32, 8);
    transpose_split_k<<<dim3(4096/32, 1024/32), tb>>>(in_proj_w, w_in_h, w_in_l, 1024, 4096);
    transpose_split_k<<<dim3( 128/32, 2048/32), tb>>>(x_proj_w,  w_x_h,  w_x_l,  2048,   96);
    transpose_split_k<<<dim3(2048/32,   64/32), tb>>>(dt_proj_w, w_dt_h, w_dt_l,   64, 2048);
    transpose_split_k<<<dim3(1024/32, 2048/32), tb>>>(out_proj_w,w_o_h,  w_o_l,  2048, 1024);
    transpose_split_k<<<dim3(4096/32, 1024/32), tb>>>(gate_w,    w_g_h,  w_g_l,  1024, 4096);
    transpose_split_k<<<dim3(4096/32, 1024/32), tb>>>(up_w,      w_u_h,  w_u_l,  1024, 4096);
    transpose_split_k<<<dim3(1024/32, 4096/32), tb>>>(down_w,    w_d_h,  w_d_l,  4096, 1024);

    // 1. input RMSNorm -> split
    rmsnorm_split_k<<<TOK, 256>>>(hidden_states, input_ln_w, ln_h, ln_l);
    // 2. in_proj
    gemm_mma<0><<<dim3(4096/128, TOK/128), 256, GSM>>>(
        ln_h, ln_l, w_in_h, w_in_l, xz, TOK, 2*DINNER, DMODEL, nullptr, nullptr);
    // 3. conv + SiLU + split; conv_state
    conv_silu_k<<<dim3(DINNER/256, SEQ, BATCH), 256>>>(xz, conv_w, conv_b, xconv, xc_h, xc_l);
    conv_state_k<<<(BATCH*DINNER*KCONV + 255)/256, 256>>>(xz, out_conv);
    // 4. x_proj (N padded to 128)
    gemm_mma<0><<<dim3(1, TOK/128), 256, GSM>>>(
        xc_h, xc_l, w_x_h, w_x_l, proj, TOK, 128, DINNER, nullptr, nullptr);
    // 5. small norms
    norms_small_k<<<TOK/8, 256>>>(proj, dt_ln_w, b_ln_w, c_ln_w, dtn_h, dtn_l, Bm, Cm);
    // 6. dt_proj + bias + softplus
    gemm_mma<1><<<dim3(DINNER/128, TOK/128), 256, GSM>>>(
        dtn_h, dtn_l, w_dt_h, w_dt_l, dt, TOK, DINNER, DTRANK, dt_proj_b, nullptr);
    // 7. selective scan
    aprep_k<<<DINNER/256, 256>>>(A_log);
    scan1_k<<<dim3(DINNER/256, NCH, BATCH), 256>>>();
    scan2_k<<<CHANNELS/256, 256>>>(out_ssm);
    scan3_k<<<dim3(DINNER/256, NCH, BATCH), 256>>>(D_skip);
    // 8. out_proj + residual
    gemm_mma<2><<<dim3(DMODEL/128, TOK/128), 256, GSM>>>(
        yg_h, yg_l, w_o_h, w_o_l, hid, TOK, DMODEL, DINNER, nullptr, hidden_states);
    // 9. MLP
    rmsnorm_split_k<<<TOK, 256>>>(hid, pre_moe_ln_w, ln_h, ln_l);
    gemm_mma<0><<<dim3(DFF/128, TOK/128), 256, GSM>>>(
        ln_h, ln_l, w_g_h, w_g_l, gate, TOK, DFF, DMODEL, nullptr, nullptr);
    gemm_mma<0><<<dim3(DFF/128, TOK/128), 256, GSM>>>(
        ln_h, ln_l, w_u_h, w_u_l, up, TOK, DFF, DMODEL, nullptr, nullptr);
    swiglu_split_k<<<(TOK*DFF)/256, 256>>>(gate, up, gu_h, gu_l, TOK*DFF);
    gemm_mma<2><<<dim3(DMODEL/128, TOK/128), 256, GSM>>>(
        gu_h, gu_l, w_d_h, w_d_l, out, TOK, DMODEL, DFF, nullptr, hid);
}

// round 4
// speedup vs baseline: 2.5868x; 1.2925x over previous
#include <cuda_runtime.h>
#include <cuda_bf16.h>
#include <cstdint>
#include <math.h>

// ---------------------------------------------------------------------------
// Problem constants
// ---------------------------------------------------------------------------
#define BATCH   2
#define SEQ     2048
#define DMODEL  1024
#define DINNER  2048
#define DSTATE  16
#define DTRANK  64
#define KCONV   4
#define DFF     4096
#define TOK     (BATCH*SEQ)          // 4096 tokens
#define NCH     16                   // scan chunks
#define CHL     128                  // chunk length
#define CHANNELS (BATCH*DINNER)      // 4096 scan channels

typedef __nv_bfloat16 bf16;

// ---------------------------------------------------------------------------
// Device scratch (static; harness forbids cudaMalloc)
// ---------------------------------------------------------------------------
__device__ float g_xz    [TOK*2*DINNER];
__device__ float g_xconv [TOK*DINNER];
__device__ float g_proj  [TOK*128];
__device__ float g_Bm    [TOK*DSTATE];
__device__ float g_Cm    [TOK*DSTATE];
__device__ float g_dt    [TOK*DINNER];
__device__ float g_hidden[TOK*DMODEL];
__device__ float g_gate  [TOK*DFF];
__device__ float g_Aneg  [DINNER*DSTATE];
__device__ int   g_afast [DINNER];
__device__ float g_Aprod [NCH*CHANNELS*DSTATE];
__device__ float g_h0    [NCH*CHANNELS*DSTATE];
__device__ float g_hin   [NCH*CHANNELS*DSTATE];

// bf16 split weights (transposed to [N,K])
__device__ bf16 wt_in_h[2*DINNER*DMODEL],  wt_in_l[2*DINNER*DMODEL];
__device__ bf16 wt_x_h [128*DINNER],       wt_x_l [128*DINNER];
__device__ bf16 wt_dt_h[DINNER*DTRANK],    wt_dt_l[DINNER*DTRANK];
__device__ bf16 wt_o_h [DMODEL*DINNER],    wt_o_l [DMODEL*DINNER];
__device__ bf16 wt_g_h [DFF*DMODEL],       wt_g_l [DFF*DMODEL];
__device__ bf16 wt_u_h [DFF*DMODEL],       wt_u_l [DFF*DMODEL];
__device__ bf16 wt_d_h [DMODEL*DFF],       wt_d_l [DMODEL*DFF];

// bf16 split activations
__device__ bf16 a_ln_h [TOK*DMODEL],  a_ln_l [TOK*DMODEL];
__device__ bf16 a_xc_h [TOK*DINNER],  a_xc_l [TOK*DINNER];
__device__ bf16 a_dtn_h[TOK*DTRANK],  a_dtn_l[TOK*DTRANK];
__device__ bf16 a_yg_h [TOK*DINNER],  a_yg_l [TOK*DINNER];
__device__ bf16 a_gu_h [TOK*DFF],     a_gu_l [TOK*DFF];

// ---------------------------------------------------------------------------
// Helpers
// ---------------------------------------------------------------------------
__device__ __forceinline__ float sigmoidf_(float x) { return 1.f / (1.f + __expf(-x)); }
__device__ __forceinline__ float siluf_(float x)    { return x * sigmoidf_(x); }
__device__ __forceinline__ float softplusf_(float x){ return x > 20.f ? x : log1pf(__expf(x)); }

__device__ __forceinline__ void split_bf16(float v, bf16& h, bf16& l) {
    h = __float2bfloat16(v);
    l = __float2bfloat16(v - __bfloat162float(h));
}

__device__ __forceinline__ uint32_t smem_u32(const void* p) {
    uint32_t a;
    asm("{ .reg .u64 t; cvta.to.shared.u64 t, %1; cvt.u32.u64 %0, t; }" : "=r"(a) : "l"(p));
    return a;
}

#define CP16(s, g) \
    asm volatile("cp.async.cg.shared.global [%0], [%1], 16;" :: "r"(s), "l"(g))
#define CP_COMMIT() asm volatile("cp.async.commit_group;" ::: "memory")
#define CP_WAIT1()  asm volatile("cp.async.wait_group 1;"  ::: "memory")

#define LDMX4(r, a)                                                              \
    asm volatile("ldmatrix.sync.aligned.m8n8.x4.shared.b16 {%0,%1,%2,%3}, [%4];" \
        : "=r"((r)[0]), "=r"((r)[1]), "=r"((r)[2]), "=r"((r)[3]) : "r"(a))

__device__ __forceinline__ void mma16816(float* c, const uint32_t* a,
                                         uint32_t b0, uint32_t b1) {
    asm volatile("mma.sync.aligned.m16n8k16.row.col.f32.bf16.bf16.f32 "
        "{%0,%1,%2,%3}, {%4,%5,%6,%7}, {%8,%9}, {%0,%1,%2,%3};"
        : "+f"(c[0]), "+f"(c[1]), "+f"(c[2]), "+f"(c[3])
        : "r"(a[0]), "r"(a[1]), "r"(a[2]), "r"(a[3]), "r"(b0), "r"(b1));
}

// Swizzled byte offset inside a 128-row x 64-byte tile (conflict-free ldmatrix)
__device__ __forceinline__ int tswz(int r, int c16) {
    return r * 64 + ((c16 ^ ((r >> 1) & 3)) << 4);
}

// ---------------------------------------------------------------------------
// bf16 x3-split GEMM on mma.sync: C[M,N] = (Ah+Al)@(Bh+Bl)^T
// Block 128x128, BK=32, 128 threads (4 warps, 2x2 grid, warp tile 64x64),
// 3-stage cp.async pipeline (96 KB smem -> 2 CTAs/SM).
// EPI: 0 none, 1 bias+softplus, 2 +residual,
//      3 swiglu fuse (v = silu(res)*acc -> bf16 split Oh/Ol, no fp32 C write),
//      4 split-K atomicAdd into C (gridDim.z slices K).
// ---------------------------------------------------------------------------
#define GSTAGES 3
#define TILEB   8192              // 128 x 32 bf16
#define STAGEB  (4*TILEB)         // Ah, Al, Bh, Bl  (32 KB)

template<int EPI>
__global__ __launch_bounds__(128, 2) void gemm_mma(
    const bf16* __restrict__ Ah, const bf16* __restrict__ Al,
    const bf16* __restrict__ Bh, const bf16* __restrict__ Bl,
    float* __restrict__ C, int M, int N, int K,
    const float* __restrict__ bias, const float* __restrict__ res,
    bf16* __restrict__ Oh, bf16* __restrict__ Ol)
{
    extern __shared__ char smem[];
    const int tid  = threadIdx.x;
    const int lane = tid & 31, wid = tid >> 5;
    const int wm = wid & 1, wn = wid >> 1;        // warp grid 2(m) x 2(n)
    const int m0 = blockIdx.y * 128, n0 = blockIdx.x * 128;
    const uint32_t sb = smem_u32(smem);

    // split-K slice
    const int Kloc  = (EPI == 4) ? (K / gridDim.z) : K;
    const int kbase = (EPI == 4) ? (blockIdx.z * Kloc) : 0;

    float acc[4][8][4];
#pragma unroll
    for (int i = 0; i < 4; i++)
#pragma unroll
        for (int j = 0; j < 8; j++)
#pragma unroll
            for (int q = 0; q < 4; q++) acc[i][j][q] = 0.f;

    const int nIters = Kloc >> 5;
    const int lrow = tid >> 2, lc16 = tid & 3;   // 4 threads cover one 64B row

    auto issue = [&](int it, int s) {
        const int kof = kbase + (it << 5);
        uint32_t d = sb + s * STAGEB;
#pragma unroll
        for (int j = 0; j < 4; j++) {
            int r = lrow + j * 32;
            int sw = tswz(r, lc16);
            size_t ga = (size_t)(m0 + r) * K + kof + lc16 * 8;
            size_t gb = (size_t)(n0 + r) * K + kof + lc16 * 8;
            CP16(d + sw,             Ah + ga);
            CP16(d + TILEB + sw,     Al + ga);
            CP16(d + 2*TILEB + sw,   Bh + gb);
            CP16(d + 3*TILEB + sw,   Bl + gb);
        }
    };

    issue(0, 0); CP_COMMIT();
    if (nIters > 1) { issue(1, 1); }
    CP_COMMIT();

    const int a_rb = wm * 64 + (lane & 15);
    const int a_cs = lane >> 4;
    const int b_rb = wn * 64 + ((lane >> 3) & 2) * 4 + (lane & 7);
    const int b_cs = (lane >> 3) & 1;

    for (int it = 0; it < nIters; ++it) {
        CP_WAIT1();
        __syncthreads();
        const uint32_t base = sb + (it % GSTAGES) * STAGEB;

#pragma unroll
        for (int ks = 0; ks < 2; ks++) {
            uint32_t ah[4][4], al[4][4];
#pragma unroll
            for (int mt = 0; mt < 4; mt++) {
                int off = tswz(a_rb + mt * 16, ks * 2 + a_cs);
                LDMX4(ah[mt], base + off);
                LDMX4(al[mt], base + TILEB + off);
            }
#pragma unroll
            for (int p = 0; p < 4; p++) {
                uint32_t bh[4], bl[4];
                int off = tswz(b_rb + p * 16, ks * 2 + b_cs);
                LDMX4(bh, base + 2*TILEB + off);
                LDMX4(bl, base + 3*TILEB + off);
#pragma unroll
                for (int mt = 0; mt < 4; mt++) {
                    mma16816(acc[mt][2*p],   ah[mt], bh[0], bh[1]);
                    mma16816(acc[mt][2*p+1], ah[mt], bh[2], bh[3]);
                    mma16816(acc[mt][2*p],   al[mt], bh[0], bh[1]);
                    mma16816(acc[mt][2*p+1], al[mt], bh[2], bh[3]);
                    mma16816(acc[mt][2*p],   ah[mt], bl[0], bl[1]);
                    mma16816(acc[mt][2*p+1], ah[mt], bl[2], bl[3]);
                }
            }
        }
        if (it + 2 < nIters) issue(it + 2, (it + 2) % GSTAGES);
        CP_COMMIT();
    }

    // Epilogue
#pragma unroll
    for (int mt = 0; mt < 4; mt++) {
        int row0 = m0 + wm * 64 + mt * 16 + (lane >> 2);
#pragma unroll
        for (int nt = 0; nt < 8; nt++) {
            int col = n0 + wn * 64 + nt * 8 + (lane & 3) * 2;
            float2 v0 = { acc[mt][nt][0], acc[mt][nt][1] };
            float2 v1 = { acc[mt][nt][2], acc[mt][nt][3] };
            size_t o0 = (size_t)row0 * N + col;
            size_t o1 = (size_t)(row0 + 8) * N + col;
            if (EPI == 1) {
                float b0 = bias[col], b1 = bias[col + 1];
                v0.x = softplusf_(v0.x + b0); v0.y = softplusf_(v0.y + b1);
                v1.x = softplusf_(v1.x + b0); v1.y = softplusf_(v1.y + b1);
            } else if (EPI == 2) {
                float2 r2;
                r2 = *reinterpret_cast<const float2*>(res + o0);
                v0.x += r2.x; v0.y += r2.y;
                r2 = *reinterpret_cast<const float2*>(res + o1);
                v1.x += r2.x; v1.y += r2.y;
            }
            if (EPI == 3) {
                // v = silu(gate) * up   -> bf16 split only
                float2 gsrc;
                gsrc = *reinterpret_cast<const float2*>(res + o0);
                v0.x = siluf_(gsrc.x) * v0.x; v0.y = siluf_(gsrc.y) * v0.y;
                gsrc = *reinterpret_cast<const float2*>(res + o1);
                v1.x = siluf_(gsrc.x) * v1.x; v1.y = siluf_(gsrc.y) * v1.y;
                bf16 h0, l0, h1, l1;
                __nv_bfloat162 hv, lv;
                split_bf16(v0.x, h0, l0); split_bf16(v0.y, h1, l1);
                hv.x = h0; hv.y = h1; lv.x = l0; lv.y = l1;
                *reinterpret_cast<__nv_bfloat162*>(Oh + o0) = hv;
                *reinterpret_cast<__nv_bfloat162*>(Ol + o0) = lv;
                split_bf16(v1.x, h0, l0); split_bf16(v1.y, h1, l1);
                hv.x = h0; hv.y = h1; lv.x = l0; lv.y = l1;
                *reinterpret_cast<__nv_bfloat162*>(Oh + o1) = hv;
                *reinterpret_cast<__nv_bfloat162*>(Ol + o1) = lv;
            } else if (EPI == 4) {
                atomicAdd(C + o0,     v0.x); atomicAdd(C + o0 + 1, v0.y);
                atomicAdd(C + o1,     v1.x); atomicAdd(C + o1 + 1, v1.y);
            } else {
                *reinterpret_cast<float2*>(C + o0) = v0;
                *reinterpret_cast<float2*>(C + o1) = v1;
            }
        }
    }
}

// ---------------------------------------------------------------------------
// Weight transpose + bf16 split: W[K,Nsrc] fp32 -> T[N,K] bf16 hi/lo (pad 0)
// ---------------------------------------------------------------------------
__global__ void transpose_split_k(const float* __restrict__ W,
                                  bf16* __restrict__ Th, bf16* __restrict__ Tl,
                                  int K, int Nsrc) {
    __shared__ float tile[32][33];
    int n0 = blockIdx.x * 32, k0 = blockIdx.y * 32;
    int tx = threadIdx.x, ty = threadIdx.y;
#pragma unroll
    for (int j = 0; j < 32; j += 8) {
        int n = n0 + tx, k = k0 + ty + j;
        tile[ty + j][tx] = (n < Nsrc) ? W[(size_t)k * Nsrc + n] : 0.f;
    }
    __syncthreads();
#pragma unroll
    for (int j = 0; j < 32; j += 8) {
        int n = n0 + ty + j, k = k0 + tx;
        float v = tile[tx][ty + j];
        bf16 h, lo; split_bf16(v, h, lo);
        Th[(size_t)n * K + k] = h;
        Tl[(size_t)n * K + k] = lo;
    }
}

// ---------------------------------------------------------------------------
// RMSNorm (1024) -> bf16 split
// ---------------------------------------------------------------------------
__global__ void rmsnorm_split_k(const float* __restrict__ x, const float* __restrict__ w,
                                bf16* __restrict__ oh, bf16* __restrict__ ol) {
    int row = blockIdx.x, tid = threadIdx.x;
    float4 v = reinterpret_cast<const float4*>(x + (size_t)row * DMODEL)[tid];
    float ss = v.x*v.x + v.y*v.y + v.z*v.z + v.w*v.w;
#pragma unroll
    for (int off = 16; off > 0; off >>= 1) ss += __shfl_xor_sync(0xffffffffu, ss, off);
    __shared__ float sred[8];
    __shared__ float sinv;
    int lane = tid & 31, wd = tid >> 5;
    if (lane == 0) sred[wd] = ss;
    __syncthreads();
    if (tid == 0) {
        float t = 0.f;
#pragma unroll
        for (int i = 0; i < 8; i++) t += sred[i];
        sinv = rsqrtf(t / (float)DMODEL + 1e-6f);
    }
    __syncthreads();
    float inv = sinv;
    float4 wv = reinterpret_cast<const float4*>(w)[tid];
    float r[4] = { v.x*inv*wv.x, v.y*inv*wv.y, v.z*inv*wv.z, v.w*inv*wv.w };
    size_t base = (size_t)row * DMODEL + tid * 4;
#pragma unroll
    for (int j = 0; j < 4; j++) {
        bf16 h, lo; split_bf16(r[j], h, lo);
        oh[base + j] = h; ol[base + j] = lo;
    }
}

// ---------------------------------------------------------------------------
// Depthwise causal conv (K=4) + bias + SiLU -> fp32 + bf16 split
// ---------------------------------------------------------------------------
__global__ void conv_silu_k(const float* __restrict__ xz, const float* __restrict__ cw,
                            const float* __restrict__ cb, float* __restrict__ out,
                            bf16* __restrict__ oh, bf16* __restrict__ ol) {
    int d = blockIdx.x * 256 + threadIdx.x;
    int t = blockIdx.y, b = blockIdx.z;
    const float* xp = xz + ((size_t)(b * SEQ + t)) * (2 * DINNER) + d;
    float w0 = cw[d*4+0], w1 = cw[d*4+1], w2 = cw[d*4+2], w3 = cw[d*4+3];
    float acc = cb[d];
    if (t >= 3) acc = fmaf(xp[-3 * 2 * DINNER], w0, acc);
    if (t >= 2) acc = fmaf(xp[-2 * 2 * DINNER], w1, acc);
    if (t >= 1) acc = fmaf(xp[-1 * 2 * DINNER], w2, acc);
    acc = fmaf(xp[0], w3, acc);
    float v = siluf_(acc);
    size_t ix = ((size_t)(b * SEQ + t)) * DINNER + d;
    out[ix] = v;
    bf16 h, lo; split_bf16(v, h, lo);
    oh[ix] = h; ol[ix] = lo;
}

__global__ void conv_state_k(const float* __restrict__ xz, float* __restrict__ oc) {
    int i = blockIdx.x * 256 + threadIdx.x;
    if (i >= BATCH * DINNER * KCONV) return;
    int k = i & 3;
    int d = (i >> 2) % DINNER;
    int b = i / (DINNER * KCONV);
    oc[i] = xz[((size_t)(b * SEQ + SEQ - KCONV + k)) * (2 * DINNER) + d];
}

// ---------------------------------------------------------------------------
// Small RMSNorms (proj stride 128): dt(64)->bf16 split, B/C(16)->fp32
// ---------------------------------------------------------------------------
__global__ void norms_small_k(const float* __restrict__ proj,
                              const float* __restrict__ wdt,
                              const float* __restrict__ wb,
                              const float* __restrict__ wc,
                              bf16* __restrict__ dth, bf16* __restrict__ dtl,
                              float* __restrict__ Bm, float* __restrict__ Cm) {
    int t = (blockIdx.x * blockDim.x + threadIdx.x) >> 5;
    int lane = threadIdx.x & 31;
    if (t >= TOK) return;
    const float* p = proj + (size_t)t * 128;
    float a = p[lane], b = p[lane + 32];
    float ss = a*a + b*b;
#pragma unroll
    for (int off = 16; off > 0; off >>= 1) ss += __shfl_xor_sync(0xffffffffu, ss, off);
    float bv = lane < 16 ? p[64 + lane] : 0.f;
    float ssb = bv * bv;
#pragma unroll
    for (int off = 16; off > 0; off >>= 1) ssb += __shfl_xor_sync(0xffffffffu, ssb, off);
    float cv = lane < 16 ? p[80 + lane] : 0.f;
    float ssc = cv * cv;
#pragma unroll
    for (int off = 16; off > 0; off >>= 1) ssc += __shfl_xor_sync(0xffffffffu, ssc, off);

    float invd = rsqrtf(ss / 64.f + 1e-6f);
    float d0 = a * invd * wdt[lane];
    float d1 = b * invd * wdt[lane + 32];
    bf16 h, lo;
    split_bf16(d0, h, lo); dth[(size_t)t*64 + lane] = h;      dtl[(size_t)t*64 + lane] = lo;
    split_bf16(d1, h, lo); dth[(size_t)t*64 + lane + 32] = h; dtl[(size_t)t*64 + lane + 32] = lo;
    if (lane < 16) {
        Bm[(size_t)t*16 + lane] = bv * rsqrtf(ssb / 16.f + 1e-6f) * wb[lane];
        Cm[(size_t)t*16 + lane] = cv * rsqrtf(ssc / 16.f + 1e-6f) * wc[lane];
    }
}

// ---------------------------------------------------------------------------
// A preprocessing + fast-path detection
// ---------------------------------------------------------------------------
__global__ void aprep_k(const float* __restrict__ A_log) {
    int d = blockIdx.x * 256 + threadIdx.x;
    if (d >= DINNER) return;
    float a[16];
#pragma unroll
    for (int n = 0; n < 16; n++) {
        a[n] = -expf(A_log[d * 16 + n]);
        g_Aneg[d * 16 + n] = a[n];
    }
    int ok = a[0] < 0.f;
#pragma unroll
    for (int n = 1; n < 16; n++) {
        float r = a[n] / a[0];
        ok = ok && (fabsf(r - (float)(n + 1)) <= 1e-4f * (float)(n + 1));
    }
    g_afast[d] = ok;
}

// ---------------------------------------------------------------------------
// Selective scan (3-phase chunked)
// ---------------------------------------------------------------------------
__global__ __launch_bounds__(256) void scan1_k() {
    __shared__ float sB[CHL * 16];
    int d = blockIdx.x * 256 + threadIdx.x;
    int c = blockIdx.y, b = blockIdx.z;
    size_t tok0 = (size_t)b * SEQ + (size_t)c * CHL;
    for (int idx = threadIdx.x; idx < CHL * 16; idx += 256)
        sB[idx] = g_Bm[tok0 * 16 + idx];
    __syncthreads();

    float h[16], Ap[16];
#pragma unroll
    for (int n = 0; n < 16; n++) { h[n] = 0.f; Ap[n] = 1.f; }
    int fast = g_afast[d];
    float A0 = g_Aneg[d * 16];

    if (fast) {
        for (int t = 0; t < CHL; t++) {
            size_t ix = (tok0 + t) * DINNER + d;
            float dtv = g_dt[ix], xv = g_xconv[ix];
            float u = dtv * xv;
            float e = __expf(dtv * A0);
            const float* Bt = &sB[t * 16];
            float p = e;
#pragma unroll
            for (int n = 0; n < 16; n++) {
                h[n] = fmaf(h[n], p, u * Bt[n]);
                Ap[n] *= p;
                p *= e;
            }
        }
    } else {
        float Ar[16];
#pragma unroll
        for (int n = 0; n < 16; n++) Ar[n] = g_Aneg[d * 16 + n];
        for (int t = 0; t < CHL; t++) {
            size_t ix = (tok0 + t) * DINNER + d;
            float dtv = g_dt[ix], xv = g_xconv[ix];
            float u = dtv * xv;
            const float* Bt = &sB[t * 16];
#pragma unroll
            for (int n = 0; n < 16; n++) {
                float da = __expf(dtv * Ar[n]);
                h[n] = fmaf(h[n], da, u * Bt[n]);
                Ap[n] *= da;
            }
        }
    }
    int ch = b * DINNER + d;
    size_t o = ((size_t)c * CHANNELS + ch) * 16;
#pragma unroll
    for (int n = 0; n < 16; n++) { g_Aprod[o + n] = Ap[n]; g_h0[o + n] = h[n]; }
}

__global__ void scan2_k(float* __restrict__ ssm_out) {
    int ch = blockIdx.x * 256 + threadIdx.x;
    if (ch >= CHANNELS) return;
    float carry[16];
#pragma unroll
    for (int n = 0; n < 16; n++) carry[n] = 0.f;
    for (int c = 0; c < NCH; c++) {
        size_t o = ((size_t)c * CHANNELS + ch) * 16;
#pragma unroll
        for (int n = 0; n < 16; n++) {
            g_hin[o + n] = carry[n];
            carry[n] = fmaf(g_Aprod[o + n], carry[n], g_h0[o + n]);
        }
    }
#pragma unroll
    for (int n = 0; n < 16; n++) ssm_out[(size_t)ch * 16 + n] = carry[n];
}

__global__ __launch_bounds__(256) void scan3_k(const float* __restrict__ Dskip) {
    __shared__ float sB[CHL * 16];
    __shared__ float sC[CHL * 16];
    int d = blockIdx.x * 256 + threadIdx.x;
    int c = blockIdx.y, b = blockIdx.z;
    size_t tok0 = (size_t)b * SEQ + (size_t)c * CHL;
    for (int idx = threadIdx.x; idx < CHL * 16; idx += 256) {
        sB[idx] = g_Bm[tok0 * 16 + idx];
        sC[idx] = g_Cm[tok0 * 16 + idx];
    }
    __syncthreads();

    int ch = b * DINNER + d;
    size_t ho = ((size_t)c * CHANNELS + ch) * 16;
    float h[16];
#pragma unroll
    for (int n = 0; n < 16; n++) h[n] = g_hin[ho + n];
    int fast = g_afast[d];
    float A0 = g_Aneg[d * 16];
    float Dk = Dskip[d];

    if (fast) {
        for (int t = 0; t < CHL; t++) {
            size_t ix = (tok0 + t) * DINNER + d;
            float dtv = g_dt[ix], xv = g_xconv[ix];
            float u = dtv * xv;
            float zv = g_xz[(tok0 + t) * (2 * DINNER) + DINNER + d];
            float e = __expf(dtv * A0);
            const float* Bt = &sB[t * 16];
            const float* Ct = &sC[t * 16];
            float p = e, y = 0.f;
#pragma unroll
            for (int n = 0; n < 16; n++) {
                h[n] = fmaf(h[n], p, u * Bt[n]);
                y = fmaf(h[n], Ct[n], y);
                p *= e;
            }
            float yv = fmaf(xv, Dk, y) * siluf_(zv);
            bf16 hh, ll; split_bf16(yv, hh, ll);
            a_yg_h[ix] = hh; a_yg_l[ix] = ll;
        }
    } else {
        float Ar[16];
#pragma unroll
        for (int n = 0; n < 16; n++) Ar[n] = g_Aneg[d * 16 + n];
        for (int t = 0; t < CHL; t++) {
            size_t ix = (tok0 + t) * DINNER + d;
            float dtv = g_dt[ix], xv = g_xconv[ix];
            float u = dtv * xv;
            float zv = g_xz[(tok0 + t) * (2 * DINNER) + DINNER + d];
            const float* Bt = &sB[t * 16];
            const float* Ct = &sC[t * 16];
            float y = 0.f;
#pragma unroll
            for (int n = 0; n < 16; n++) {
                float da = __expf(dtv * Ar[n]);
                h[n] = fmaf(h[n], da, u * Bt[n]);
                y = fmaf(h[n], Ct[n], y);
            }
            float yv = fmaf(xv, Dk, y) * siluf_(zv);
            bf16 hh, ll; split_bf16(yv, hh, ll);
            a_yg_h[ix] = hh; a_yg_l[ix] = ll;
        }
    }
}

// ---------------------------------------------------------------------------
// Launch
// ---------------------------------------------------------------------------
extern "C" void kernel_launch(void* const* d_in, const int* in_sizes, int n_in,
                              void* d_out, int out_size) {
    (void)in_sizes; (void)n_in; (void)out_size;
    const float* hidden_states = (const float*)d_in[0];
    const float* in_proj_w     = (const float*)d_in[1];
    const float* conv_w        = (const float*)d_in[2];
    const float* conv_b        = (const float*)d_in[3];
    const float* x_proj_w      = (const float*)d_in[4];
    const float* dt_proj_w     = (const float*)d_in[5];
    const float* dt_proj_b     = (const float*)d_in[6];
    const float* dt_ln_w       = (const float*)d_in[7];
    const float* b_ln_w        = (const float*)d_in[8];
    const float* c_ln_w        = (const float*)d_in[9];
    const float* A_log         = (const float*)d_in[10];
    const float* D_skip        = (const float*)d_in[11];
    const float* out_proj_w    = (const float*)d_in[12];
    const float* input_ln_w    = (const float*)d_in[13];
    const float* pre_moe_ln_w  = (const float*)d_in[14];
    const float* gate_w        = (const float*)d_in[15];
    const float* up_w          = (const float*)d_in[16];
    const float* down_w        = (const float*)d_in[17];

    float* out      = (float*)d_out;
    float* out_conv = out + (size_t)TOK * DMODEL;
    float* out_ssm  = out_conv + BATCH * DINNER * KCONV;

    float *xz, *xconv, *proj, *Bm, *Cm, *dt, *hid, *gate;
    cudaGetSymbolAddress((void**)&xz,    g_xz);
    cudaGetSymbolAddress((void**)&xconv, g_xconv);
    cudaGetSymbolAddress((void**)&proj,  g_proj);
    cudaGetSymbolAddress((void**)&Bm,    g_Bm);
    cudaGetSymbolAddress((void**)&Cm,    g_Cm);
    cudaGetSymbolAddress((void**)&dt,    g_dt);
    cudaGetSymbolAddress((void**)&hid,   g_hidden);
    cudaGetSymbolAddress((void**)&gate,  g_gate);
    bf16 *w_in_h,*w_in_l,*w_x_h,*w_x_l,*w_dt_h,*w_dt_l,*w_o_h,*w_o_l,
         *w_g_h,*w_g_l,*w_u_h,*w_u_l,*w_d_h,*w_d_l;
    cudaGetSymbolAddress((void**)&w_in_h, wt_in_h); cudaGetSymbolAddress((void**)&w_in_l, wt_in_l);
    cudaGetSymbolAddress((void**)&w_x_h,  wt_x_h ); cudaGetSymbolAddress((void**)&w_x_l,  wt_x_l );
    cudaGetSymbolAddress((void**)&w_dt_h, wt_dt_h); cudaGetSymbolAddress((void**)&w_dt_l, wt_dt_l);
    cudaGetSymbolAddress((void**)&w_o_h,  wt_o_h ); cudaGetSymbolAddress((void**)&w_o_l,  wt_o_l );
    cudaGetSymbolAddress((void**)&w_g_h,  wt_g_h ); cudaGetSymbolAddress((void**)&w_g_l,  wt_g_l );
    cudaGetSymbolAddress((void**)&w_u_h,  wt_u_h ); cudaGetSymbolAddress((void**)&w_u_l,  wt_u_l );
    cudaGetSymbolAddress((void**)&w_d_h,  wt_d_h ); cudaGetSymbolAddress((void**)&w_d_l,  wt_d_l );
    bf16 *ln_h,*ln_l,*xc_h,*xc_l,*dtn_h,*dtn_l,*yg_h,*yg_l,*gu_h,*gu_l;
    cudaGetSymbolAddress((void**)&ln_h,  a_ln_h ); cudaGetSymbolAddress((void**)&ln_l,  a_ln_l );
    cudaGetSymbolAddress((void**)&xc_h,  a_xc_h ); cudaGetSymbolAddress((void**)&xc_l,  a_xc_l );
    cudaGetSymbolAddress((void**)&dtn_h, a_dtn_h); cudaGetSymbolAddress((void**)&dtn_l, a_dtn_l);
    cudaGetSymbolAddress((void**)&yg_h,  a_yg_h ); cudaGetSymbolAddress((void**)&yg_l,  a_yg_l );
    cudaGetSymbolAddress((void**)&gu_h,  a_gu_h ); cudaGetSymbolAddress((void**)&gu_l,  a_gu_l );

    constexpr size_t GSM = GSTAGES * STAGEB;   // 98304 bytes
    cudaFuncSetAttribute(gemm_mma<0>, cudaFuncAttributeMaxDynamicSharedMemorySize, GSM);
    cudaFuncSetAttribute(gemm_mma<1>, cudaFuncAttributeMaxDynamicSharedMemorySize, GSM);
    cudaFuncSetAttribute(gemm_mma<2>, cudaFuncAttributeMaxDynamicSharedMemorySize, GSM);
    cudaFuncSetAttribute(gemm_mma<3>, cudaFuncAttributeMaxDynamicSharedMemorySize, GSM);
    cudaFuncSetAttribute(gemm_mma<4>, cudaFuncAttributeMaxDynamicSharedMemorySize, GSM);

    // Weight transposes + splits
    dim3 tb(32, 8);
    transpose_split_k<<<dim3(4096/32, 1024/32), tb>>>(in_proj_w, w_in_h, w_in_l, 1024, 4096);
    transpose_split_k<<<dim3( 128/32, 2048/32), tb>>>(x_proj_w,  w_x_h,  w_x_l,  2048,   96);
    transpose_split_k<<<dim3(2048/32,   64/32), tb>>>(dt_proj_w, w_dt_h, w_dt_l,   64, 2048);
    transpose_split_k<<<dim3(1024/32, 2048/32), tb>>>(out_proj_w,w_o_h,  w_o_l,  2048, 1024);
    transpose_split_k<<<dim3(4096/32, 1024/32), tb>>>(gate_w,    w_g_h,  w_g_l,  1024, 4096);
    transpose_split_k<<<dim3(4096/32, 1024/32), tb>>>(up_w,      w_u_h,  w_u_l,  1024, 4096);
    transpose_split_k<<<dim3(1024/32, 4096/32), tb>>>(down_w,    w_d_h,  w_d_l,  4096, 1024);

    // 1. input RMSNorm -> split
    rmsnorm_split_k<<<TOK, 256>>>(hidden_states, input_ln_w, ln_h, ln_l);
    // 2. in_proj
    gemm_mma<0><<<dim3(4096/128, TOK/128), 128, GSM>>>(
        ln_h, ln_l, w_in_h, w_in_l, xz, TOK, 2*DINNER, DMODEL,
        nullptr, nullptr, nullptr, nullptr);
    // 3. conv + SiLU + split; conv_state
    conv_silu_k<<<dim3(DINNER/256, SEQ, BATCH), 256>>>(xz, conv_w, conv_b, xconv, xc_h, xc_l);
    conv_state_k<<<(BATCH*DINNER*KCONV + 255)/256, 256>>>(xz, out_conv);
    // 4. x_proj (N padded to 128), split-K x4
    cudaMemsetAsync(proj, 0, (size_t)TOK * 128 * sizeof(float), 0);
    gemm_mma<4><<<dim3(1, TOK/128, 4), 128, GSM>>>(
        xc_h, xc_l, w_x_h, w_x_l, proj, TOK, 128, DINNER,
        nullptr, nullptr, nullptr, nullptr);
    // 5. small norms
    norms_small_k<<<TOK/8, 256>>>(proj, dt_ln_w, b_ln_w, c_ln_w, dtn_h, dtn_l, Bm, Cm);
    // 6. dt_proj + bias + softplus
    gemm_mma<1><<<dim3(DINNER/128, TOK/128), 128, GSM>>>(
        dtn_h, dtn_l, w_dt_h, w_dt_l, dt, TOK, DINNER, DTRANK,
        dt_proj_b, nullptr, nullptr, nullptr);
    // 7. selective scan
    aprep_k<<<DINNER/256, 256>>>(A_log);
    scan1_k<<<dim3(DINNER/256, NCH, BATCH), 256>>>();
    scan2_k<<<CHANNELS/256, 256>>>(out_ssm);
    scan3_k<<<dim3(DINNER/256, NCH, BATCH), 256>>>(D_skip);
    // 8. out_proj + residual
    gemm_mma<2><<<dim3(DMODEL/128, TOK/128), 128, GSM>>>(
        yg_h, yg_l, w_o_h, w_o_l, hid, TOK, DMODEL, DINNER,
        nullptr, hidden_states, nullptr, nullptr);
    // 9. MLP
    rmsnorm_split_k<<<TOK, 256>>>(hid, pre_moe_ln_w, ln_h, ln_l);
    gemm_mma<0><<<dim3(DFF/128, TOK/128), 128, GSM>>>(
        ln_h, ln_l, w_g_h, w_g_l, gate, TOK, DFF, DMODEL,
        nullptr, nullptr, nullptr, nullptr);
    gemm_mma<3><<<dim3(DFF/128, TOK/128), 128, GSM>>>(
        ln_h, ln_l, w_u_h, w_u_l, nullptr, TOK, DFF, DMODEL,
        nullptr, gate, gu_h, gu_l);
    gemm_mma<2><<<dim3(DMODEL/128, TOK/128), 128, GSM>>>(
        gu_h, gu_l, w_d_h, w_d_l, out, TOK, DMODEL, DFF,
        nullptr, hid, nullptr, nullptr);
}

// round 5
// speedup vs baseline: 3.2344x; 1.2503x over previous
#include <cuda_runtime.h>
#include <cuda_bf16.h>
#include <cuda_fp16.h>
#include <cstdint>
#include <math.h>

// ---------------------------------------------------------------------------
// Problem constants
// ---------------------------------------------------------------------------
#define BATCH   2
#define SEQ     2048
#define DMODEL  1024
#define DINNER  2048
#define DSTATE  16
#define DTRANK  64
#define KCONV   4
#define DFF     4096
#define TOK     (BATCH*SEQ)          // 4096 tokens
#define NCH     16                   // scan chunks
#define CHL     128                  // chunk length
#define CHANNELS (BATCH*DINNER)      // 4096 scan channels

typedef __half fp16;

// ---------------------------------------------------------------------------
// Device scratch (static; harness forbids cudaMalloc)
// ---------------------------------------------------------------------------
__device__ float g_xz    [TOK*2*DINNER];
__device__ float g_xconv [TOK*DINNER];
__device__ float g_proj  [TOK*128];
__device__ float g_Bm    [TOK*DSTATE];
__device__ float g_Cm    [TOK*DSTATE];
__device__ float g_dt    [TOK*DINNER];
__device__ float g_hidden[TOK*DMODEL];
__device__ float g_gate  [TOK*DFF];
__device__ float g_Aneg  [DINNER*DSTATE];
__device__ int   g_afast [DINNER];
__device__ float g_Aprod [NCH*CHANNELS*DSTATE];
__device__ float g_h0    [NCH*CHANNELS*DSTATE];
__device__ float g_hin   [NCH*CHANNELS*DSTATE];

// fp16 split weights (transposed to [N,K]): W = Wh + Wl
__device__ fp16 wt_in_h[2*DINNER*DMODEL],  wt_in_l[2*DINNER*DMODEL];
__device__ fp16 wt_x_h [128*DINNER],       wt_x_l [128*DINNER];
__device__ fp16 wt_dt_h[DINNER*DTRANK],    wt_dt_l[DINNER*DTRANK];
__device__ fp16 wt_o_h [DMODEL*DINNER],    wt_o_l [DMODEL*DINNER];
__device__ fp16 wt_g_h [DFF*DMODEL],       wt_g_l [DFF*DMODEL];
__device__ fp16 wt_u_h [DFF*DMODEL],       wt_u_l [DFF*DMODEL];
__device__ fp16 wt_d_h [DMODEL*DFF],       wt_d_l [DMODEL*DFF];

// fp16 activations (single precision copy)
__device__ fp16 a_ln [TOK*DMODEL];
__device__ fp16 a_xc [TOK*DINNER];
__device__ fp16 a_dtn[TOK*DTRANK];
__device__ fp16 a_yg [TOK*DINNER];
__device__ fp16 a_gu [TOK*DFF];

// ---------------------------------------------------------------------------
// Helpers
// ---------------------------------------------------------------------------
__device__ __forceinline__ float sigmoidf_(float x) { return 1.f / (1.f + __expf(-x)); }
__device__ __forceinline__ float siluf_(float x)    { return x * sigmoidf_(x); }
__device__ __forceinline__ float softplusf_(float x){ return x > 20.f ? x : log1pf(__expf(x)); }

__device__ __forceinline__ void split_fp16(float v, fp16& h, fp16& l) {
    h = __float2half_rn(v);
    l = __float2half_rn(v - __half2float(h));
}

__device__ __forceinline__ uint32_t smem_u32(const void* p) {
    uint32_t a;
    asm("{ .reg .u64 t; cvta.to.shared.u64 t, %1; cvt.u32.u64 %0, t; }" : "=r"(a) : "l"(p));
    return a;
}

#define CP16(s, g) \
    asm volatile("cp.async.cg.shared.global [%0], [%1], 16;" :: "r"(s), "l"(g))
#define CP_COMMIT() asm volatile("cp.async.commit_group;" ::: "memory")
#define CP_WAIT2()  asm volatile("cp.async.wait_group 2;"  ::: "memory")

#define LDMX4(r, a)                                                              \
    asm volatile("ldmatrix.sync.aligned.m8n8.x4.shared.b16 {%0,%1,%2,%3}, [%4];" \
        : "=r"((r)[0]), "=r"((r)[1]), "=r"((r)[2]), "=r"((r)[3]) : "r"(a))

__device__ __forceinline__ void mma16816(float* c, const uint32_t* a,
                                         uint32_t b0, uint32_t b1) {
    asm volatile("mma.sync.aligned.m16n8k16.row.col.f32.f16.f16.f32 "
        "{%0,%1,%2,%3}, {%4,%5,%6,%7}, {%8,%9}, {%0,%1,%2,%3};"
        : "+f"(c[0]), "+f"(c[1]), "+f"(c[2]), "+f"(c[3])
        : "r"(a[0]), "r"(a[1]), "r"(a[2]), "r"(a[3]), "r"(b0), "r"(b1));
}

// Swizzled byte offset inside a 128-row x 64-byte tile (conflict-free ldmatrix)
__device__ __forceinline__ int tswz(int r, int c16) {
    return r * 64 + ((c16 ^ ((r >> 1) & 3)) << 4);
}

// ---------------------------------------------------------------------------
// fp16 2-term GEMM on mma.sync: C[M,N] = A[M,K] @ (Bh+Bl)[N,K]^T
// Block 128x128, BK=32, 128 threads (4 warps 2x2, warp tile 64x64),
// 4-stage cp.async pipeline (96 KB smem -> 2 CTAs/SM).
// EPI: 0 none, 1 bias+softplus, 2 +residual,
//      3 swiglu fuse (v = silu(res)*acc -> fp16 Oh, no fp32 C write),
//      4 split-K atomicAdd into C (gridDim.z slices K).
// ---------------------------------------------------------------------------
#define GSTAGES 4
#define TILEB   8192              // 128 x 32 fp16
#define STAGEB  (3*TILEB)         // A, Bh, Bl  (24 KB)

template<int EPI>
__global__ __launch_bounds__(128, 2) void gemm_mma(
    const fp16* __restrict__ A,
    const fp16* __restrict__ Bh, const fp16* __restrict__ Bl,
    float* __restrict__ C, int M, int N, int K,
    const float* __restrict__ bias, const float* __restrict__ res,
    fp16* __restrict__ Oh)
{
    extern __shared__ char smem[];
    const int tid  = threadIdx.x;
    const int lane = tid & 31, wid = tid >> 5;
    const int wm = wid & 1, wn = wid >> 1;        // warp grid 2(m) x 2(n)
    const int m0 = blockIdx.y * 128, n0 = blockIdx.x * 128;
    const uint32_t sb = smem_u32(smem);

    const int Kloc  = (EPI == 4) ? (K / gridDim.z) : K;
    const int kbase = (EPI == 4) ? (blockIdx.z * Kloc) : 0;

    float acc[4][8][4];
#pragma unroll
    for (int i = 0; i < 4; i++)
#pragma unroll
        for (int j = 0; j < 8; j++)
#pragma unroll
            for (int q = 0; q < 4; q++) acc[i][j][q] = 0.f;

    const int nIters = Kloc >> 5;
    const int lrow = tid >> 2, lc16 = tid & 3;   // 4 threads cover one 64B row

    auto issue = [&](int it, int s) {
        const int kof = kbase + (it << 5);
        uint32_t d = sb + s * STAGEB;
#pragma unroll
        for (int j = 0; j < 4; j++) {
            int r = lrow + j * 32;
            int sw = tswz(r, lc16);
            size_t ga = (size_t)(m0 + r) * K + kof + lc16 * 8;
            size_t gb = (size_t)(n0 + r) * K + kof + lc16 * 8;
            CP16(d + sw,             A  + ga);
            CP16(d + TILEB + sw,     Bh + gb);
            CP16(d + 2*TILEB + sw,   Bl + gb);
        }
    };

#pragma unroll
    for (int s = 0; s < 3; s++) {
        if (s < nIters) issue(s, s);
        CP_COMMIT();
    }

    const int a_rb = wm * 64 + (lane & 15);
    const int a_cs = lane >> 4;
    const int b_rb = wn * 64 + ((lane >> 3) & 2) * 4 + (lane & 7);
    const int b_cs = (lane >> 3) & 1;

    for (int it = 0; it < nIters; ++it) {
        CP_WAIT2();
        __syncthreads();
        const uint32_t base = sb + (it & (GSTAGES - 1)) * STAGEB;

#pragma unroll
        for (int ks = 0; ks < 2; ks++) {
            uint32_t ah[4][4];
#pragma unroll
            for (int mt = 0; mt < 4; mt++) {
                int off = tswz(a_rb + mt * 16, ks * 2 + a_cs);
                LDMX4(ah[mt], base + off);
            }
#pragma unroll
            for (int p = 0; p < 4; p++) {
                uint32_t bh[4], bl[4];
                int off = tswz(b_rb + p * 16, ks * 2 + b_cs);
                LDMX4(bh, base + TILEB + off);
                LDMX4(bl, base + 2*TILEB + off);
#pragma unroll
                for (int mt = 0; mt < 4; mt++) {
                    mma16816(acc[mt][2*p],   ah[mt], bh[0], bh[1]);
                    mma16816(acc[mt][2*p+1], ah[mt], bh[2], bh[3]);
                    mma16816(acc[mt][2*p],   ah[mt], bl[0], bl[1]);
                    mma16816(acc[mt][2*p+1], ah[mt], bl[2], bl[3]);
                }
            }
        }
        if (it + 3 < nIters) issue(it + 3, (it + 3) & (GSTAGES - 1));
        CP_COMMIT();
    }

    // Epilogue
#pragma unroll
    for (int mt = 0; mt < 4; mt++) {
        int row0 = m0 + wm * 64 + mt * 16 + (lane >> 2);
#pragma unroll
        for (int nt = 0; nt < 8; nt++) {
            int col = n0 + wn * 64 + nt * 8 + (lane & 3) * 2;
            float2 v0 = { acc[mt][nt][0], acc[mt][nt][1] };
            float2 v1 = { acc[mt][nt][2], acc[mt][nt][3] };
            size_t o0 = (size_t)row0 * N + col;
            size_t o1 = (size_t)(row0 + 8) * N + col;
            if (EPI == 1) {
                float b0 = bias[col], b1 = bias[col + 1];
                v0.x = softplusf_(v0.x + b0); v0.y = softplusf_(v0.y + b1);
                v1.x = softplusf_(v1.x + b0); v1.y = softplusf_(v1.y + b1);
            } else if (EPI == 2) {
                float2 r2;
                r2 = *reinterpret_cast<const float2*>(res + o0);
                v0.x += r2.x; v0.y += r2.y;
                r2 = *reinterpret_cast<const float2*>(res + o1);
                v1.x += r2.x; v1.y += r2.y;
            }
            if (EPI == 3) {
                float2 gsrc;
                gsrc = *reinterpret_cast<const float2*>(res + o0);
                v0.x = siluf_(gsrc.x) * v0.x; v0.y = siluf_(gsrc.y) * v0.y;
                gsrc = *reinterpret_cast<const float2*>(res + o1);
                v1.x = siluf_(gsrc.x) * v1.x; v1.y = siluf_(gsrc.y) * v1.y;
                __half2 hv;
                hv.x = __float2half_rn(v0.x); hv.y = __float2half_rn(v0.y);
                *reinterpret_cast<__half2*>(Oh + o0) = hv;
                hv.x = __float2half_rn(v1.x); hv.y = __float2half_rn(v1.y);
                *reinterpret_cast<__half2*>(Oh + o1) = hv;
            } else if (EPI == 4) {
                atomicAdd(C + o0,     v0.x); atomicAdd(C + o0 + 1, v0.y);
                atomicAdd(C + o1,     v1.x); atomicAdd(C + o1 + 1, v1.y);
            } else {
                *reinterpret_cast<float2*>(C + o0) = v0;
                *reinterpret_cast<float2*>(C + o1) = v1;
            }
        }
    }
}

// ---------------------------------------------------------------------------
// Weight transpose + fp16 split: W[K,Nsrc] fp32 -> T[N,K] fp16 hi/lo (pad 0)
// ---------------------------------------------------------------------------
__global__ void transpose_split_k(const float* __restrict__ W,
                                  fp16* __restrict__ Th, fp16* __restrict__ Tl,
                                  int K, int Nsrc) {
    __shared__ float tile[32][33];
    int n0 = blockIdx.x * 32, k0 = blockIdx.y * 32;
    int tx = threadIdx.x, ty = threadIdx.y;
#pragma unroll
    for (int j = 0; j < 32; j += 8) {
        int n = n0 + tx, k = k0 + ty + j;
        tile[ty + j][tx] = (n < Nsrc) ? W[(size_t)k * Nsrc + n] : 0.f;
    }
    __syncthreads();
#pragma unroll
    for (int j = 0; j < 32; j += 8) {
        int n = n0 + ty + j, k = k0 + tx;
        float v = tile[tx][ty + j];
        fp16 h, lo; split_fp16(v, h, lo);
        Th[(size_t)n * K + k] = h;
        Tl[(size_t)n * K + k] = lo;
    }
}

// ---------------------------------------------------------------------------
// RMSNorm (1024) -> fp16
// ---------------------------------------------------------------------------
__global__ void rmsnorm_h_k(const float* __restrict__ x, const float* __restrict__ w,
                            fp16* __restrict__ o) {
    int row = blockIdx.x, tid = threadIdx.x;
    float4 v = reinterpret_cast<const float4*>(x + (size_t)row * DMODEL)[tid];
    float ss = v.x*v.x + v.y*v.y + v.z*v.z + v.w*v.w;
#pragma unroll
    for (int off = 16; off > 0; off >>= 1) ss += __shfl_xor_sync(0xffffffffu, ss, off);
    __shared__ float sred[8];
    __shared__ float sinv;
    int lane = tid & 31, wd = tid >> 5;
    if (lane == 0) sred[wd] = ss;
    __syncthreads();
    if (tid == 0) {
        float t = 0.f;
#pragma unroll
        for (int i = 0; i < 8; i++) t += sred[i];
        sinv = rsqrtf(t / (float)DMODEL + 1e-6f);
    }
    __syncthreads();
    float inv = sinv;
    float4 wv = reinterpret_cast<const float4*>(w)[tid];
    __half2 h0, h1;
    h0.x = __float2half_rn(v.x*inv*wv.x); h0.y = __float2half_rn(v.y*inv*wv.y);
    h1.x = __float2half_rn(v.z*inv*wv.z); h1.y = __float2half_rn(v.w*inv*wv.w);
    size_t base = (size_t)row * DMODEL + tid * 4;
    *reinterpret_cast<__half2*>(o + base)     = h0;
    *reinterpret_cast<__half2*>(o + base + 2) = h1;
}

// ---------------------------------------------------------------------------
// Depthwise causal conv (K=4) + bias + SiLU, 16 timesteps per thread.
// ---------------------------------------------------------------------------
__global__ void conv_silu_k(const float* __restrict__ xz, const float* __restrict__ cw,
                            const float* __restrict__ cb, float* __restrict__ out,
                            fp16* __restrict__ oh) {
    int d = blockIdx.x * 256 + threadIdx.x;
    int t0 = blockIdx.y * 16, b = blockIdx.z;
    const int STRIDE = 2 * DINNER;
    const float* xp = xz + ((size_t)(b * SEQ + t0)) * STRIDE + d;
    float w0 = cw[d*4+0], w1 = cw[d*4+1], w2 = cw[d*4+2], w3 = cw[d*4+3];
    float bias = cb[d];
    float xm3 = (t0 >= 3) ? xp[-3 * STRIDE] : 0.f;
    float xm2 = (t0 >= 2) ? xp[-2 * STRIDE] : 0.f;
    float xm1 = (t0 >= 1) ? xp[-1 * STRIDE] : 0.f;
    size_t ox = ((size_t)(b * SEQ + t0)) * DINNER + d;
#pragma unroll
    for (int tt = 0; tt < 16; tt++) {
        float xt = xp[tt * STRIDE];
        float acc = bias + w0*xm3 + w1*xm2 + w2*xm1 + w3*xt;
        float v = siluf_(acc);
        out[ox + tt * DINNER] = v;
        oh[ox + tt * DINNER] = __float2half_rn(v);
        xm3 = xm2; xm2 = xm1; xm1 = xt;
    }
}

__global__ void conv_state_k(const float* __restrict__ xz, float* __restrict__ oc) {
    int i = blockIdx.x * 256 + threadIdx.x;
    if (i >= BATCH * DINNER * KCONV) return;
    int k = i & 3;
    int d = (i >> 2) % DINNER;
    int b = i / (DINNER * KCONV);
    oc[i] = xz[((size_t)(b * SEQ + SEQ - KCONV + k)) * (2 * DINNER) + d];
}

// ---------------------------------------------------------------------------
// Small RMSNorms (proj stride 128): dt(64)->fp16, B/C(16)->fp32
// ---------------------------------------------------------------------------
__global__ void norms_small_k(const float* __restrict__ proj,
                              const float* __restrict__ wdt,
                              const float* __restrict__ wb,
                              const float* __restrict__ wc,
                              fp16* __restrict__ dth,
                              float* __restrict__ Bm, float* __restrict__ Cm) {
    int t = (blockIdx.x * blockDim.x + threadIdx.x) >> 5;
    int lane = threadIdx.x & 31;
    if (t >= TOK) return;
    const float* p = proj + (size_t)t * 128;
    float a = p[lane], b = p[lane + 32];
    float ss = a*a + b*b;
#pragma unroll
    for (int off = 16; off > 0; off >>= 1) ss += __shfl_xor_sync(0xffffffffu, ss, off);
    float bv = lane < 16 ? p[64 + lane] : 0.f;
    float ssb = bv * bv;
#pragma unroll
    for (int off = 16; off > 0; off >>= 1) ssb += __shfl_xor_sync(0xffffffffu, ssb, off);
    float cv = lane < 16 ? p[80 + lane] : 0.f;
    float ssc = cv * cv;
#pragma unroll
    for (int off = 16; off > 0; off >>= 1) ssc += __shfl_xor_sync(0xffffffffu, ssc, off);

    float invd = rsqrtf(ss / 64.f + 1e-6f);
    dth[(size_t)t*64 + lane]      = __float2half_rn(a * invd * wdt[lane]);
    dth[(size_t)t*64 + lane + 32] = __float2half_rn(b * invd * wdt[lane + 32]);
    if (lane < 16) {
        Bm[(size_t)t*16 + lane] = bv * rsqrtf(ssb / 16.f + 1e-6f) * wb[lane];
        Cm[(size_t)t*16 + lane] = cv * rsqrtf(ssc / 16.f + 1e-6f) * wc[lane];
    }
}

// ---------------------------------------------------------------------------
// A preprocessing + fast-path detection
// ---------------------------------------------------------------------------
__global__ void aprep_k(const float* __restrict__ A_log) {
    int d = blockIdx.x * 256 + threadIdx.x;
    if (d >= DINNER) return;
    float a[16];
#pragma unroll
    for (int n = 0; n < 16; n++) {
        a[n] = -expf(A_log[d * 16 + n]);
        g_Aneg[d * 16 + n] = a[n];
    }
    int ok = a[0] < 0.f;
#pragma unroll
    for (int n = 1; n < 16; n++) {
        float r = a[n] / a[0];
        ok = ok && (fabsf(r - (float)(n + 1)) <= 1e-4f * (float)(n + 1));
    }
    g_afast[d] = ok;
}

// ---------------------------------------------------------------------------
// Selective scan (3-phase chunked)
// ---------------------------------------------------------------------------
__global__ __launch_bounds__(256) void scan1_k() {
    __shared__ float sB[CHL * 16];
    int d = blockIdx.x * 256 + threadIdx.x;
    int c = blockIdx.y, b = blockIdx.z;
    size_t tok0 = (size_t)b * SEQ + (size_t)c * CHL;
    for (int idx = threadIdx.x; idx < CHL * 16; idx += 256)
        sB[idx] = g_Bm[tok0 * 16 + idx];
    __syncthreads();

    float h[16], Ap[16];
#pragma unroll
    for (int n = 0; n < 16; n++) { h[n] = 0.f; Ap[n] = 1.f; }
    int fast = g_afast[d];
    float A0 = g_Aneg[d * 16];

    if (fast) {
        for (int t = 0; t < CHL; t++) {
            size_t ix = (tok0 + t) * DINNER + d;
            float dtv = g_dt[ix], xv = g_xconv[ix];
            float u = dtv * xv;
            float e = __expf(dtv * A0);
            const float* Bt = &sB[t * 16];
            float p = e;
#pragma unroll
            for (int n = 0; n < 16; n++) {
                h[n] = fmaf(h[n], p, u * Bt[n]);
                Ap[n] *= p;
                p *= e;
            }
        }
    } else {
        float Ar[16];
#pragma unroll
        for (int n = 0; n < 16; n++) Ar[n] = g_Aneg[d * 16 + n];
        for (int t = 0; t < CHL; t++) {
            size_t ix = (tok0 + t) * DINNER + d;
            float dtv = g_dt[ix], xv = g_xconv[ix];
            float u = dtv * xv;
            const float* Bt = &sB[t * 16];
#pragma unroll
            for (int n = 0; n < 16; n++) {
                float da = __expf(dtv * Ar[n]);
                h[n] = fmaf(h[n], da, u * Bt[n]);
                Ap[n] *= da;
            }
        }
    }
    int ch = b * DINNER + d;
    size_t o = ((size_t)c * CHANNELS + ch) * 16;
#pragma unroll
    for (int n = 0; n < 16; n++) { g_Aprod[o + n] = Ap[n]; g_h0[o + n] = h[n]; }
}

__global__ void scan2_k(float* __restrict__ ssm_out) {
    int ch = blockIdx.x * 256 + threadIdx.x;
    if (ch >= CHANNELS) return;
    float carry[16];
#pragma unroll
    for (int n = 0; n < 16; n++) carry[n] = 0.f;
    for (int c = 0; c < NCH; c++) {
        size_t o = ((size_t)c * CHANNELS + ch) * 16;
#pragma unroll
        for (int n = 0; n < 16; n++) {
            g_hin[o + n] = carry[n];
            carry[n] = fmaf(g_Aprod[o + n], carry[n], g_h0[o + n]);
        }
    }
#pragma unroll
    for (int n = 0; n < 16; n++) ssm_out[(size_t)ch * 16 + n] = carry[n];
}

__global__ __launch_bounds__(256) void scan3_k(const float* __restrict__ Dskip) {
    __shared__ float sB[CHL * 16];
    __shared__ float sC[CHL * 16];
    int d = blockIdx.x * 256 + threadIdx.x;
    int c = blockIdx.y, b = blockIdx.z;
    size_t tok0 = (size_t)b * SEQ + (size_t)c * CHL;
    for (int idx = threadIdx.x; idx < CHL * 16; idx += 256) {
        sB[idx] = g_Bm[tok0 * 16 + idx];
        sC[idx] = g_Cm[tok0 * 16 + idx];
    }
    __syncthreads();

    int ch = b * DINNER + d;
    size_t ho = ((size_t)c * CHANNELS + ch) * 16;
    float h[16];
#pragma unroll
    for (int n = 0; n < 16; n++) h[n] = g_hin[ho + n];
    int fast = g_afast[d];
    float A0 = g_Aneg[d * 16];
    float Dk = Dskip[d];

    if (fast) {
        for (int t = 0; t < CHL; t++) {
            size_t ix = (tok0 + t) * DINNER + d;
            float dtv = g_dt[ix], xv = g_xconv[ix];
            float u = dtv * xv;
            float zv = g_xz[(tok0 + t) * (2 * DINNER) + DINNER + d];
            float e = __expf(dtv * A0);
            const float* Bt = &sB[t * 16];
            const float* Ct = &sC[t * 16];
            float p = e, y = 0.f;
#pragma unroll
            for (int n = 0; n < 16; n++) {
                h[n] = fmaf(h[n], p, u * Bt[n]);
                y = fmaf(h[n], Ct[n], y);
                p *= e;
            }
            float yv = fmaf(xv, Dk, y) * siluf_(zv);
            a_yg[ix] = __float2half_rn(yv);
        }
    } else {
        float Ar[16];
#pragma unroll
        for (int n = 0; n < 16; n++) Ar[n] = g_Aneg[d * 16 + n];
        for (int t = 0; t < CHL; t++) {
            size_t ix = (tok0 + t) * DINNER + d;
            float dtv = g_dt[ix], xv = g_xconv[ix];
            float u = dtv * xv;
            float zv = g_xz[(tok0 + t) * (2 * DINNER) + DINNER + d];
            const float* Bt = &sB[t * 16];
            const float* Ct = &sC[t * 16];
            float y = 0.f;
#pragma unroll
            for (int n = 0; n < 16; n++) {
                float da = __expf(dtv * Ar[n]);
                h[n] = fmaf(h[n], da, u * Bt[n]);
                y = fmaf(h[n], Ct[n], y);
            }
            float yv = fmaf(xv, Dk, y) * siluf_(zv);
            a_yg[ix] = __float2half_rn(yv);
        }
    }
}

// ---------------------------------------------------------------------------
// Launch
// ---------------------------------------------------------------------------
extern "C" void kernel_launch(void* const* d_in, const int* in_sizes, int n_in,
                              void* d_out, int out_size) {
    (void)in_sizes; (void)n_in; (void)out_size;
    const float* hidden_states = (const float*)d_in[0];
    const float* in_proj_w     = (const float*)d_in[1];
    const float* conv_w        = (const float*)d_in[2];
    const float* conv_b        = (const float*)d_in[3];
    const float* x_proj_w      = (const float*)d_in[4];
    const float* dt_proj_w     = (const float*)d_in[5];
    const float* dt_proj_b     = (const float*)d_in[6];
    const float* dt_ln_w       = (const float*)d_in[7];
    const float* b_ln_w        = (const float*)d_in[8];
    const float* c_ln_w        = (const float*)d_in[9];
    const float* A_log         = (const float*)d_in[10];
    const float* D_skip        = (const float*)d_in[11];
    const float* out_proj_w    = (const float*)d_in[12];
    const float* input_ln_w    = (const float*)d_in[13];
    const float* pre_moe_ln_w  = (const float*)d_in[14];
    const float* gate_w        = (const float*)d_in[15];
    const float* up_w          = (const float*)d_in[16];
    const float* down_w        = (const float*)d_in[17];

    float* out      = (float*)d_out;
    float* out_conv = out + (size_t)TOK * DMODEL;
    float* out_ssm  = out_conv + BATCH * DINNER * KCONV;

    float *xz, *xconv, *proj, *Bm, *Cm, *dt, *hid, *gate;
    cudaGetSymbolAddress((void**)&xz,    g_xz);
    cudaGetSymbolAddress((void**)&xconv, g_xconv);
    cudaGetSymbolAddress((void**)&proj,  g_proj);
    cudaGetSymbolAddress((void**)&Bm,    g_Bm);
    cudaGetSymbolAddress((void**)&Cm,    g_Cm);
    cudaGetSymbolAddress((void**)&dt,    g_dt);
    cudaGetSymbolAddress((void**)&hid,   g_hidden);
    cudaGetSymbolAddress((void**)&gate,  g_gate);
    fp16 *w_in_h,*w_in_l,*w_x_h,*w_x_l,*w_dt_h,*w_dt_l,*w_o_h,*w_o_l,
         *w_g_h,*w_g_l,*w_u_h,*w_u_l,*w_d_h,*w_d_l;
    cudaGetSymbolAddress((void**)&w_in_h, wt_in_h); cudaGetSymbolAddress((void**)&w_in_l, wt_in_l);
    cudaGetSymbolAddress((void**)&w_x_h,  wt_x_h ); cudaGetSymbolAddress((void**)&w_x_l,  wt_x_l );
    cudaGetSymbolAddress((void**)&w_dt_h, wt_dt_h); cudaGetSymbolAddress((void**)&w_dt_l, wt_dt_l);
    cudaGetSymbolAddress((void**)&w_o_h,  wt_o_h ); cudaGetSymbolAddress((void**)&w_o_l,  wt_o_l );
    cudaGetSymbolAddress((void**)&w_g_h,  wt_g_h ); cudaGetSymbolAddress((void**)&w_g_l,  wt_g_l );
    cudaGetSymbolAddress((void**)&w_u_h,  wt_u_h ); cudaGetSymbolAddress((void**)&w_u_l,  wt_u_l );
    cudaGetSymbolAddress((void**)&w_d_h,  wt_d_h ); cudaGetSymbolAddress((void**)&w_d_l,  wt_d_l );
    fp16 *ln, *xc, *dtn, *yg, *gu;
    cudaGetSymbolAddress((void**)&ln,  a_ln );
    cudaGetSymbolAddress((void**)&xc,  a_xc );
    cudaGetSymbolAddress((void**)&dtn, a_dtn);
    cudaGetSymbolAddress((void**)&yg,  a_yg );
    cudaGetSymbolAddress((void**)&gu,  a_gu );

    constexpr size_t GSM = GSTAGES * STAGEB;   // 98304 bytes
    cudaFuncSetAttribute(gemm_mma<0>, cudaFuncAttributeMaxDynamicSharedMemorySize, GSM);
    cudaFuncSetAttribute(gemm_mma<1>, cudaFuncAttributeMaxDynamicSharedMemorySize, GSM);
    cudaFuncSetAttribute(gemm_mma<2>, cudaFuncAttributeMaxDynamicSharedMemorySize, GSM);
    cudaFuncSetAttribute(gemm_mma<3>, cudaFuncAttributeMaxDynamicSharedMemorySize, GSM);
    cudaFuncSetAttribute(gemm_mma<4>, cudaFuncAttributeMaxDynamicSharedMemorySize, GSM);

    // Weight transposes + splits
    dim3 tb(32, 8);
    transpose_split_k<<<dim3(4096/32, 1024/32), tb>>>(in_proj_w, w_in_h, w_in_l, 1024, 4096);
    transpose_split_k<<<dim3( 128/32, 2048/32), tb>>>(x_proj_w,  w_x_h,  w_x_l,  2048,   96);
    transpose_split_k<<<dim3(2048/32,   64/32), tb>>>(dt_proj_w, w_dt_h, w_dt_l,   64, 2048);
    transpose_split_k<<<dim3(1024/32, 2048/32), tb>>>(out_proj_w,w_o_h,  w_o_l,  2048, 1024);
    transpose_split_k<<<dim3(4096/32, 1024/32), tb>>>(gate_w,    w_g_h,  w_g_l,  1024, 4096);
    transpose_split_k<<<dim3(4096/32, 1024/32), tb>>>(up_w,      w_u_h,  w_u_l,  1024, 4096);
    transpose_split_k<<<dim3(1024/32, 4096/32), tb>>>(down_w,    w_d_h,  w_d_l,  4096, 1024);

    // 1. input RMSNorm -> fp16
    rmsnorm_h_k<<<TOK, 256>>>(hidden_states, input_ln_w, ln);
    // 2. in_proj
    gemm_mma<0><<<dim3(4096/128, TOK/128), 128, GSM>>>(
        ln, w_in_h, w_in_l, xz, TOK, 2*DINNER, DMODEL, nullptr, nullptr, nullptr);
    // 3. conv + SiLU; conv_state
    conv_silu_k<<<dim3(DINNER/256, SEQ/16, BATCH), 256>>>(xz, conv_w, conv_b, xconv, xc);
    conv_state_k<<<(BATCH*DINNER*KCONV + 255)/256, 256>>>(xz, out_conv);
    // 4. x_proj (N padded to 128), split-K x4
    cudaMemsetAsync(proj, 0, (size_t)TOK * 128 * sizeof(float), 0);
    gemm_mma<4><<<dim3(1, TOK/128, 4), 128, GSM>>>(
        xc, w_x_h, w_x_l, proj, TOK, 128, DINNER, nullptr, nullptr, nullptr);
    // 5. small norms
    norms_small_k<<<TOK/8, 256>>>(proj, dt_ln_w, b_ln_w, c_ln_w, dtn, Bm, Cm);
    // 6. dt_proj + bias + softplus
    gemm_mma<1><<<dim3(DINNER/128, TOK/128), 128, GSM>>>(
        dtn, w_dt_h, w_dt_l, dt, TOK, DINNER, DTRANK, dt_proj_b, nullptr, nullptr);
    // 7. selective scan
    aprep_k<<<DINNER/256, 256>>>(A_log);
    scan1_k<<<dim3(DINNER/256, NCH, BATCH), 256>>>();
    scan2_k<<<CHANNELS/256, 256>>>(out_ssm);
    scan3_k<<<dim3(DINNER/256, NCH, BATCH), 256>>>(D_skip);
    // 8. out_proj + residual
    gemm_mma<2><<<dim3(DMODEL/128, TOK/128), 128, GSM>>>(
        yg, w_o_h, w_o_l, hid, TOK, DMODEL, DINNER, nullptr, hidden_states, nullptr);
    // 9. MLP
    rmsnorm_h_k<<<TOK, 256>>>(hid, pre_moe_ln_w, ln);
    gemm_mma<0><<<dim3(DFF/128, TOK/128), 128, GSM>>>(
        ln, w_g_h, w_g_l, gate, TOK, DFF, DMODEL, nullptr, nullptr, nullptr);
    gemm_mma<3><<<dim3(DFF/128, TOK/128), 128, GSM>>>(
        ln, w_u_h, w_u_l, nullptr, TOK, DFF, DMODEL, nullptr, gate, gu);
    gemm_mma<2><<<dim3(DMODEL/128, TOK/128), 128, GSM>>>(
        gu, w_d_h, w_d_l, out, TOK, DMODEL, DFF, nullptr, hid, nullptr);
}